// round 7
// baseline (speedup 1.0000x reference)
#include <cuda_runtime.h>
#include <cuda_bf16.h>
#include <math.h>
#include <stdint.h>

#define BSZ 4
#define SEQ 2048
#define EMB 1024
#define NH 16
#define HD 64
#define MTOT (BSZ*SEQ)   // 8192

// ---------------- scratch (__device__ globals; no allocs allowed) ----------
static __device__ __align__(256) __nv_bfloat16 g_xh[(size_t)MTOT*EMB];
static __device__ __align__(256) __nv_bfloat16 g_xl[(size_t)MTOT*EMB];
static __device__ __align__(256) __nv_bfloat16 g_wh[4][(size_t)EMB*EMB];
static __device__ __align__(256) __nv_bfloat16 g_wl[4][(size_t)EMB*EMB];
static __device__ __align__(256) __nv_bfloat16 g_Qh[(size_t)MTOT*EMB];
static __device__ __align__(256) __nv_bfloat16 g_Ql[(size_t)MTOT*EMB];
static __device__ __align__(256) __nv_bfloat16 g_Kh[(size_t)MTOT*EMB];
static __device__ __align__(256) __nv_bfloat16 g_Kl[(size_t)MTOT*EMB];
static __device__ __align__(256) __nv_bfloat16 g_Vh[(size_t)MTOT*EMB];
static __device__ __align__(256) __nv_bfloat16 g_Vl[(size_t)MTOT*EMB];

// ---------------- helpers --------------------------------------------------
__device__ __forceinline__ uint32_t smem_u32(const void* p) {
    uint32_t a;
    asm("{ .reg .u64 t; cvta.to.shared.u64 t, %1; cvt.u32.u64 %0, t; }"
        : "=r"(a) : "l"(p));
    return a;
}
__device__ __forceinline__ void cp16(uint32_t dst, const void* src) {
    asm volatile("cp.async.cg.shared.global [%0], [%1], 16;" :: "r"(dst), "l"(src));
}
#define CP_COMMIT() asm volatile("cp.async.commit_group;" ::: "memory")
#define CP_WAIT1()  asm volatile("cp.async.wait_group 1;" ::: "memory")
#define CP_WAIT0()  asm volatile("cp.async.wait_group 0;" ::: "memory")

__device__ __forceinline__ void ldsm4(uint32_t r[4], uint32_t a) {
    asm volatile("ldmatrix.sync.aligned.m8n8.x4.shared.b16 {%0,%1,%2,%3}, [%4];"
        : "=r"(r[0]), "=r"(r[1]), "=r"(r[2]), "=r"(r[3]) : "r"(a));
}
__device__ __forceinline__ void ldsm4t(uint32_t r[4], uint32_t a) {
    asm volatile("ldmatrix.sync.aligned.m8n8.x4.trans.shared.b16 {%0,%1,%2,%3}, [%4];"
        : "=r"(r[0]), "=r"(r[1]), "=r"(r[2]), "=r"(r[3]) : "r"(a));
}
__device__ __forceinline__ void mma16816(float c[4], const uint32_t a[4],
                                         uint32_t b0, uint32_t b1) {
    asm volatile("mma.sync.aligned.m16n8k16.row.col.f32.bf16.bf16.f32 "
        "{%0,%1,%2,%3}, {%4,%5,%6,%7}, {%8,%9}, {%0,%1,%2,%3};"
        : "+f"(c[0]), "+f"(c[1]), "+f"(c[2]), "+f"(c[3])
        : "r"(a[0]), "r"(a[1]), "r"(a[2]), "r"(a[3]), "r"(b0), "r"(b1));
}
__device__ __forceinline__ void split2(float v0, float v1, uint32_t& h, uint32_t& l) {
    __nv_bfloat162 hh = __floats2bfloat162_rn(v0, v1);
    float r0 = v0 - __bfloat162float(hh.x);
    float r1 = v1 - __bfloat162float(hh.y);
    __nv_bfloat162 ll = __floats2bfloat162_rn(r0, r1);
    h = *reinterpret_cast<uint32_t*>(&hh);
    l = *reinterpret_cast<uint32_t*>(&ll);
}
// byte offset of 16B chunk (row, ch) in a [rows x 64] bf16 tile, XOR-swizzled
#define SWZ(r, ch) (((r) << 7) | (((unsigned)((ch) ^ (r)) & 7u) << 4))

// ---------------------------------------------------------------------------
__global__ __launch_bounds__(256)
void split_kernel(const float* __restrict__ src,
                  __nv_bfloat16* __restrict__ hi, __nv_bfloat16* __restrict__ lo) {
    size_t i = (size_t)blockIdx.x * 256 + threadIdx.x;
    float4 v = ((const float4*)src)[i];
    uint32_t h0, l0, h1, l1;
    split2(v.x, v.y, h0, l0);
    split2(v.z, v.w, h1, l1);
    ((uint32_t*)hi)[2*i+0] = h0;  ((uint32_t*)hi)[2*i+1] = h1;
    ((uint32_t*)lo)[2*i+0] = l0;  ((uint32_t*)lo)[2*i+1] = l1;
}

// all 4 weight transposes in one launch (grid.z selects W)
__global__ __launch_bounds__(256)
void tsplit4_kernel(const float* __restrict__ W0, const float* __restrict__ W1,
                    const float* __restrict__ W2, const float* __restrict__ W3,
                    __nv_bfloat16* __restrict__ ThB, __nv_bfloat16* __restrict__ TlB) {
    __shared__ float sm[32][33];
    const int tx = threadIdx.x, ty = threadIdx.y;
    const int n0 = blockIdx.x * 32, k0 = blockIdx.y * 32;
    const int z = blockIdx.z;
    const float* W = (z == 0) ? W0 : (z == 1 ? W1 : (z == 2 ? W2 : W3));
    __nv_bfloat16* Th = ThB + (size_t)z * EMB * EMB;
    __nv_bfloat16* Tl = TlB + (size_t)z * EMB * EMB;
#pragma unroll
    for (int r = ty; r < 32; r += 8)
        sm[r][tx] = W[(size_t)(k0 + r) * EMB + n0 + tx];
    __syncthreads();
#pragma unroll
    for (int r = ty; r < 32; r += 8) {
        float v = sm[tx][r];
        __nv_bfloat16 h = __float2bfloat16_rn(v);
        __nv_bfloat16 l = __float2bfloat16_rn(v - __bfloat162float(h));
        Th[(size_t)(n0 + r) * EMB + k0 + tx] = h;
        Tl[(size_t)(n0 + r) * EMB + k0 + tx] = l;
    }
}

// ---------------------------------------------------------------------------
// bf16x3 warp-MMA GEMM, cp.async 3-stage pipeline (unchanged from R6 WIN).
// ---------------------------------------------------------------------------
template<int HEADOUT>
__global__ __launch_bounds__(256, 1)
void gemm_mma(const __nv_bfloat16* __restrict__ Ah, const __nv_bfloat16* __restrict__ Al,
              const __nv_bfloat16* __restrict__ WhBase, const __nv_bfloat16* __restrict__ WlBase,
              const float* __restrict__ b0p, const float* __restrict__ b1p,
              const float* __restrict__ b2p, float* __restrict__ Co,
              __nv_bfloat16* __restrict__ C0h, __nv_bfloat16* __restrict__ C0l,
              __nv_bfloat16* __restrict__ C1h, __nv_bfloat16* __restrict__ C1l,
              __nv_bfloat16* __restrict__ C2h, __nv_bfloat16* __restrict__ C2l) {
    extern __shared__ __align__(128) char smem[];
    const uint32_t sb = smem_u32(smem);
    const int t = threadIdx.x, lane = t & 31, w = t >> 5;
    const int wm = (w & 3) * 32, wn = (w >> 2) * 64;
    const int m0 = blockIdx.y << 7, n0 = blockIdx.x << 7;
    const int z = HEADOUT ? blockIdx.z : 0;

    const __nv_bfloat16* Bh = WhBase + (size_t)z * EMB * EMB;
    const __nv_bfloat16* Bl = WlBase + (size_t)z * EMB * EMB;
    const float* bias = (z == 0) ? b0p : (z == 1 ? b1p : b2p);
    __nv_bfloat16* Ch = (z == 0) ? C0h : (z == 1 ? C1h : C2h);
    __nv_bfloat16* Cl = (z == 0) ? C0l : (z == 1 ? C1l : C2l);

    auto issue = [&](int kb, int st) {
        const uint32_t s0 = sb + st * 65536;
        const int kc = kb << 6;
#pragma unroll
        for (int i = 0; i < 4; i++) {
            int idx = t + (i << 8);
            int row = idx >> 3, ch = idx & 7;
            int so = SWZ(row, ch);
            size_t ga = (size_t)(m0 + row) * EMB + kc + (ch << 3);
            size_t gb = (size_t)(n0 + row) * EMB + kc + (ch << 3);
            cp16(s0 +         so, Ah + ga);
            cp16(s0 + 16384 + so, Al + ga);
            cp16(s0 + 32768 + so, Bh + gb);
            cp16(s0 + 49152 + so, Bl + gb);
        }
    };

    float c[2][8][4];
#pragma unroll
    for (int i = 0; i < 2; i++)
#pragma unroll
        for (int j = 0; j < 8; j++)
#pragma unroll
            for (int k = 0; k < 4; k++) c[i][j][k] = 0.f;

    issue(0, 0); CP_COMMIT();
    issue(1, 1); CP_COMMIT();

    for (int kb = 0; kb < 16; kb++) {
        CP_WAIT1();
        __syncthreads();
        if (kb + 2 < 16) issue(kb + 2, (kb + 2) % 3);
        CP_COMMIT();

        const uint32_t s0 = sb + (kb % 3) * 65536;
        const uint32_t sAh = s0, sAl = s0 + 16384, sBh = s0 + 32768, sBl = s0 + 49152;
#pragma unroll
        for (int s = 0; s < 4; s++) {
            const int ch = 2 * s + (lane >> 4);
            uint32_t ah[2][4], al[2][4];
#pragma unroll
            for (int mt = 0; mt < 2; mt++) {
                int r = wm + mt * 16 + (lane & 15);
                ldsm4(ah[mt], sAh + SWZ(r, ch));
                ldsm4(al[mt], sAl + SWZ(r, ch));
            }
#pragma unroll
            for (int g = 0; g < 4; g++) {
                int r = wn + g * 16 + (lane & 15);
                uint32_t bh[4], bl[4];
                ldsm4(bh, sBh + SWZ(r, ch));
                ldsm4(bl, sBl + SWZ(r, ch));
#pragma unroll
                for (int mt = 0; mt < 2; mt++) {
                    mma16816(c[mt][2*g],   ah[mt], bh[0], bh[2]);
                    mma16816(c[mt][2*g+1], ah[mt], bh[1], bh[3]);
                    mma16816(c[mt][2*g],   ah[mt], bl[0], bl[2]);
                    mma16816(c[mt][2*g+1], ah[mt], bl[1], bl[3]);
                    mma16816(c[mt][2*g],   al[mt], bh[0], bh[2]);
                    mma16816(c[mt][2*g+1], al[mt], bh[1], bh[3]);
                }
            }
        }
    }

#pragma unroll
    for (int mt = 0; mt < 2; mt++) {
#pragma unroll
        for (int nt = 0; nt < 8; nt++) {
            const int col = n0 + wn + nt * 8 + ((lane & 3) << 1);
            const float b0 = bias[col], b1 = bias[col + 1];
            const int r0 = m0 + wm + mt * 16 + (lane >> 2);
#pragma unroll
            for (int half = 0; half < 2; half++) {
                const int r = r0 + half * 8;
                const float v0 = c[mt][nt][half*2+0] + b0;
                const float v1 = c[mt][nt][half*2+1] + b1;
                if (HEADOUT) {
                    uint32_t h2, l2;
                    split2(v0, v1, h2, l2);
                    const int bb = r >> 11, srow = r & 2047;
                    const int hd = col >> 6, d = col & 63;
                    const size_t off = (((size_t)(bb * NH + hd)) * SEQ + srow) * HD + d;
                    *(uint32_t*)(Ch + off) = h2;
                    *(uint32_t*)(Cl + off) = l2;
                } else {
                    *(float2*)(Co + (size_t)r * EMB + col) = make_float2(v0, v1);
                }
            }
        }
    }
}

// ---------------------------------------------------------------------------
// Flash attention, warp-MMA bf16x3. R7: 256-query block, 8 warps x m32
// (2 x m16 sub-tiles per warp) -> K/V ldmatrix amortized over 2 q-subtiles,
// flipping the kernel from smem-crossbar-bound to tensor-bound.
// smem: Qh 32K | Ql 32K | KV stage0 32K | KV stage1 32K | mask bias 8K = 136KB.
// KV stage: Kh 0 | Kl 8K | Vh 16K | Vl 24K.
// ---------------------------------------------------------------------------
__global__ __launch_bounds__(256, 1)
void attn_mma(const int* __restrict__ mask) {
    extern __shared__ __align__(128) char smem[];
    const uint32_t sQh = smem_u32(smem);
    const uint32_t sQl = sQh + 32768;
    const uint32_t sKV = sQh + 65536;
    float* smb = (float*)(smem + 131072);   // 2048 floats mask bias

    const int t = threadIdx.x, lane = t & 31, w = t >> 5;
    const int qb = blockIdx.x, h = blockIdx.y, b = blockIdx.z;
    const size_t base = ((size_t)(b * NH + h)) * SEQ * HD;

    auto issue_kv = [&](int kb, int st) {
        const uint32_t s0 = sKV + st * 32768;
#pragma unroll
        for (int i = 0; i < 2; i++) {
            int idx = t + (i << 8);          // 0..511
            int row = idx >> 3, ch = idx & 7;
            int so = SWZ(row, ch);
            size_t ga = base + (size_t)(kb * 64 + row) * HD + (ch << 3);
            cp16(s0 +         so, g_Kh + ga);
            cp16(s0 +  8192 + so, g_Kl + ga);
            cp16(s0 + 16384 + so, g_Vh + ga);
            cp16(s0 + 24576 + so, g_Vl + ga);
        }
    };

    // prologue: Q tile (256 x 64 hi/lo) + mask bias + KV chunk 0
#pragma unroll
    for (int i = 0; i < 8; i++) {
        int idx = t + (i << 8);              // 0..2047
        int row = idx >> 3, ch = idx & 7;
        int so = SWZ(row, ch);
        size_t ga = base + (size_t)(qb * 256 + row) * HD + (ch << 3);
        cp16(sQh + so, g_Qh + ga);
        cp16(sQl + so, g_Ql + ga);
    }
    {
        const int4* m4 = (const int4*)(mask + b * SEQ);
#pragma unroll
        for (int i = 0; i < 2; i++) {
            int idx = t + (i << 8);
            int4 mm = m4[idx];
            smb[idx*4+0] = mm.x ? 0.f : -1.0e9f;
            smb[idx*4+1] = mm.y ? 0.f : -1.0e9f;
            smb[idx*4+2] = mm.z ? 0.f : -1.0e9f;
            smb[idx*4+3] = mm.w ? 0.f : -1.0e9f;
        }
    }
    issue_kv(0, 0); CP_COMMIT();

    float o[2][8][4];
#pragma unroll
    for (int mt = 0; mt < 2; mt++)
#pragma unroll
        for (int i = 0; i < 8; i++)
#pragma unroll
            for (int j = 0; j < 4; j++) o[mt][i][j] = 0.f;
    float mrow[2][2] = {{-INFINITY, -INFINITY}, {-INFINITY, -INFINITY}};
    float lsum[2][2] = {{0.f, 0.f}, {0.f, 0.f}};

    for (int kb = 0; kb < SEQ / 64; kb++) {
        CP_WAIT0();
        __syncthreads();
        if (kb + 1 < SEQ / 64) issue_kv(kb + 1, (kb + 1) & 1);
        CP_COMMIT();

        const uint32_t s0 = sKV + (kb & 1) * 32768;
        const uint32_t sKh = s0, sKl = s0 + 8192, sVh = s0 + 16384, sVl = s0 + 24576;

        // ---- S = Q K^T (bf16x3), m32 per warp ----
        float c[2][8][4];
#pragma unroll
        for (int mt = 0; mt < 2; mt++)
#pragma unroll
            for (int i = 0; i < 8; i++)
#pragma unroll
                for (int j = 0; j < 4; j++) c[mt][i][j] = 0.f;
#pragma unroll
        for (int s = 0; s < 4; s++) {
            const int ch = 2 * s + (lane >> 4);
            uint32_t ah[2][4], al[2][4];
#pragma unroll
            for (int mt = 0; mt < 2; mt++) {
                const int rq = w * 32 + mt * 16 + (lane & 15);
                ldsm4(ah[mt], sQh + SWZ(rq, ch));
                ldsm4(al[mt], sQl + SWZ(rq, ch));
            }
#pragma unroll
            for (int g = 0; g < 4; g++) {
                const int rk = g * 16 + (lane & 15);
                uint32_t bh[4], bl[4];
                ldsm4(bh, sKh + SWZ(rk, ch));
                ldsm4(bl, sKl + SWZ(rk, ch));
#pragma unroll
                for (int mt = 0; mt < 2; mt++) {
                    mma16816(c[mt][2*g],   ah[mt], bh[0], bh[2]);
                    mma16816(c[mt][2*g+1], ah[mt], bh[1], bh[3]);
                    mma16816(c[mt][2*g],   ah[mt], bl[0], bl[2]);
                    mma16816(c[mt][2*g+1], ah[mt], bl[1], bl[3]);
                    mma16816(c[mt][2*g],   al[mt], bh[0], bh[2]);
                    mma16816(c[mt][2*g+1], al[mt], bh[1], bh[3]);
                }
            }
        }

        // ---- scale + mask bias, online softmax, rescale o (per mt) ----
        const int cb = (lane & 3) << 1;
        const float* mbt = smb + kb * 64;
#pragma unroll
        for (int mt = 0; mt < 2; mt++) {
#pragma unroll
            for (int nt = 0; nt < 8; nt++) {
                const float m0v = mbt[nt * 8 + cb], m1v = mbt[nt * 8 + cb + 1];
                c[mt][nt][0] = fmaf(c[mt][nt][0], 0.125f, m0v);
                c[mt][nt][1] = fmaf(c[mt][nt][1], 0.125f, m1v);
                c[mt][nt][2] = fmaf(c[mt][nt][2], 0.125f, m0v);
                c[mt][nt][3] = fmaf(c[mt][nt][3], 0.125f, m1v);
            }
            float mxA = -INFINITY, mxB = -INFINITY;
#pragma unroll
            for (int nt = 0; nt < 8; nt++) {
                mxA = fmaxf(mxA, fmaxf(c[mt][nt][0], c[mt][nt][1]));
                mxB = fmaxf(mxB, fmaxf(c[mt][nt][2], c[mt][nt][3]));
            }
#pragma unroll
            for (int off = 1; off < 4; off <<= 1) {
                mxA = fmaxf(mxA, __shfl_xor_sync(0xffffffffu, mxA, off));
                mxB = fmaxf(mxB, __shfl_xor_sync(0xffffffffu, mxB, off));
            }
            const float nmA = fmaxf(mrow[mt][0], mxA), nmB = fmaxf(mrow[mt][1], mxB);
            const float scA = __expf(mrow[mt][0] - nmA), scB = __expf(mrow[mt][1] - nmB);
            mrow[mt][0] = nmA; mrow[mt][1] = nmB;
            float sA = 0.f, sB = 0.f;
#pragma unroll
            for (int nt = 0; nt < 8; nt++) {
                c[mt][nt][0] = __expf(c[mt][nt][0] - nmA);
                c[mt][nt][1] = __expf(c[mt][nt][1] - nmA);
                c[mt][nt][2] = __expf(c[mt][nt][2] - nmB);
                c[mt][nt][3] = __expf(c[mt][nt][3] - nmB);
                sA += c[mt][nt][0] + c[mt][nt][1];
                sB += c[mt][nt][2] + c[mt][nt][3];
            }
#pragma unroll
            for (int off = 1; off < 4; off <<= 1) {
                sA += __shfl_xor_sync(0xffffffffu, sA, off);
                sB += __shfl_xor_sync(0xffffffffu, sB, off);
            }
            lsum[mt][0] = lsum[mt][0] * scA + sA;
            lsum[mt][1] = lsum[mt][1] * scB + sB;
#pragma unroll
            for (int nt = 0; nt < 8; nt++) {
                o[mt][nt][0] *= scA; o[mt][nt][1] *= scA;
                o[mt][nt][2] *= scB; o[mt][nt][3] *= scB;
            }
        }

        // ---- O += P V (V fragments shared across both m16 sub-tiles) ----
#pragma unroll
        for (int kt = 0; kt < 4; kt++) {
            uint32_t ph[2][4], pl[2][4];
#pragma unroll
            for (int mt = 0; mt < 2; mt++) {
                split2(c[mt][2*kt][0],   c[mt][2*kt][1],   ph[mt][0], pl[mt][0]);
                split2(c[mt][2*kt][2],   c[mt][2*kt][3],   ph[mt][1], pl[mt][1]);
                split2(c[mt][2*kt+1][0], c[mt][2*kt+1][1], ph[mt][2], pl[mt][2]);
                split2(c[mt][2*kt+1][2], c[mt][2*kt+1][3], ph[mt][3], pl[mt][3]);
            }
            const int rv = kt * 16 + (lane & 15);
#pragma unroll
            for (int g = 0; g < 4; g++) {
                const int chv = 2 * g + (lane >> 4);
                uint32_t vh[4], vl[4];
                ldsm4t(vh, sVh + SWZ(rv, chv));
                ldsm4t(vl, sVl + SWZ(rv, chv));
#pragma unroll
                for (int mt = 0; mt < 2; mt++) {
                    mma16816(o[mt][2*g],   ph[mt], vh[0], vh[1]);
                    mma16816(o[mt][2*g+1], ph[mt], vh[2], vh[3]);
                    mma16816(o[mt][2*g],   ph[mt], vl[0], vl[1]);
                    mma16816(o[mt][2*g+1], ph[mt], vl[2], vl[3]);
                    mma16816(o[mt][2*g],   pl[mt], vh[0], vh[1]);
                    mma16816(o[mt][2*g+1], pl[mt], vh[2], vh[3]);
                }
            }
        }
    }

    // ---- epilogue: normalize, split, write bf16 hi/lo [B,S,E] ----
    const int colb = (lane & 3) << 1;
#pragma unroll
    for (int mt = 0; mt < 2; mt++) {
        const float iA = 1.f / lsum[mt][0], iB = 1.f / lsum[mt][1];
        const int rA = qb * 256 + w * 32 + mt * 16 + (lane >> 2);
#pragma unroll
        for (int nt = 0; nt < 8; nt++) {
            const int col = h * HD + nt * 8 + colb;
            uint32_t h2, l2;
            split2(o[mt][nt][0] * iA, o[mt][nt][1] * iA, h2, l2);
            size_t off = ((size_t)b * SEQ + rA) * EMB + col;
            *(uint32_t*)(g_xh + off) = h2;
            *(uint32_t*)(g_xl + off) = l2;
            split2(o[mt][nt][2] * iB, o[mt][nt][3] * iB, h2, l2);
            off = ((size_t)b * SEQ + rA + 8) * EMB + col;
            *(uint32_t*)(g_xh + off) = h2;
            *(uint32_t*)(g_xl + off) = l2;
        }
    }
}

// ---------------------------------------------------------------------------
extern "C" void kernel_launch(void* const* d_in, const int* in_sizes, int n_in,
                              void* d_out, int out_size) {
    const float* x  = (const float*)d_in[0];
    const int*  mask = (const int*)d_in[1];
    const float* Wq = (const float*)d_in[2];
    const float* bq = (const float*)d_in[3];
    const float* Wk = (const float*)d_in[4];
    const float* bk = (const float*)d_in[5];
    const float* Wv = (const float*)d_in[6];
    const float* bv = (const float*)d_in[7];
    const float* Wo = (const float*)d_in[8];
    const float* bo = (const float*)d_in[9];

    __nv_bfloat16 *xh, *xl, *wh, *wl, *Qh, *Ql, *Kh, *Kl, *Vh, *Vl;
    cudaGetSymbolAddress((void**)&xh, g_xh);
    cudaGetSymbolAddress((void**)&xl, g_xl);
    cudaGetSymbolAddress((void**)&wh, g_wh);
    cudaGetSymbolAddress((void**)&wl, g_wl);
    cudaGetSymbolAddress((void**)&Qh, g_Qh);
    cudaGetSymbolAddress((void**)&Ql, g_Ql);
    cudaGetSymbolAddress((void**)&Kh, g_Kh);
    cudaGetSymbolAddress((void**)&Kl, g_Kl);
    cudaGetSymbolAddress((void**)&Vh, g_Vh);
    cudaGetSymbolAddress((void**)&Vl, g_Vl);
    const size_t WS = (size_t)EMB * EMB;

    const int GEMM_SMEM = 3 * 65536;           // 192KB
    const int ATTN_SMEM = 131072 + 8192;       // 136KB
    cudaFuncSetAttribute(gemm_mma<1>, cudaFuncAttributeMaxDynamicSharedMemorySize, GEMM_SMEM);
    cudaFuncSetAttribute(gemm_mma<0>, cudaFuncAttributeMaxDynamicSharedMemorySize, GEMM_SMEM);
    cudaFuncSetAttribute(attn_mma,    cudaFuncAttributeMaxDynamicSharedMemorySize, ATTN_SMEM);

    // input split + all 4 weight transpose/splits in one launch
    split_kernel<<<(MTOT*EMB)/4/256, 256>>>(x, xh, xl);
    tsplit4_kernel<<<dim3(32,32,4), dim3(32,8)>>>(Wq, Wk, Wv, Wo, wh, wl);

    // fused QKV projection (z = 0,1,2 -> Q,K,V), bf16 hi/lo out in [B,H,S,D]
    gemm_mma<1><<<dim3(EMB/128, MTOT/128, 3), 256, GEMM_SMEM>>>(
        xh, xl, wh, wl, bq, bk, bv, nullptr, Qh, Ql, Kh, Kl, Vh, Vl);

    // attention (256-query blocks) -> bf16 hi/lo activations into xh/xl
    attn_mma<<<dim3(SEQ/256, NH, BSZ), 256, ATTN_SMEM>>>(mask);

    // O projection -> fp32 d_out
    gemm_mma<0><<<dim3(EMB/128, MTOT/128, 1), 256, GEMM_SMEM>>>(
        xh, xl, wh + 3*WS, wl + 3*WS, bo, bo, bo, (float*)d_out,
        nullptr, nullptr, nullptr, nullptr, nullptr, nullptr);
}

// round 9
// speedup vs baseline: 1.0903x; 1.0903x over previous
#include <cuda_runtime.h>
#include <cuda_bf16.h>
#include <math.h>
#include <stdint.h>

#define BSZ 4
#define SEQ 2048
#define EMB 1024
#define NH 16
#define HD 64
#define MTOT (BSZ*SEQ)   // 8192

// ---------------- scratch (__device__ globals; no allocs allowed) ----------
static __device__ __align__(256) __nv_bfloat16 g_xh[(size_t)MTOT*EMB];
static __device__ __align__(256) __nv_bfloat16 g_xl[(size_t)MTOT*EMB];
static __device__ __align__(256) __nv_bfloat16 g_wh[4][(size_t)EMB*EMB];
static __device__ __align__(256) __nv_bfloat16 g_wl[4][(size_t)EMB*EMB];
static __device__ __align__(256) __nv_bfloat16 g_Qh[(size_t)MTOT*EMB];
static __device__ __align__(256) __nv_bfloat16 g_Ql[(size_t)MTOT*EMB];
static __device__ __align__(256) __nv_bfloat16 g_Kh[(size_t)MTOT*EMB];
static __device__ __align__(256) __nv_bfloat16 g_Kl[(size_t)MTOT*EMB];
static __device__ __align__(256) __nv_bfloat16 g_Vh[(size_t)MTOT*EMB];
static __device__ __align__(256) __nv_bfloat16 g_Vl[(size_t)MTOT*EMB];

// ---------------- helpers --------------------------------------------------
__device__ __forceinline__ uint32_t smem_u32(const void* p) {
    uint32_t a;
    asm("{ .reg .u64 t; cvta.to.shared.u64 t, %1; cvt.u32.u64 %0, t; }"
        : "=r"(a) : "l"(p));
    return a;
}
__device__ __forceinline__ void cp16(uint32_t dst, const void* src) {
    asm volatile("cp.async.cg.shared.global [%0], [%1], 16;" :: "r"(dst), "l"(src));
}
#define CP_COMMIT() asm volatile("cp.async.commit_group;" ::: "memory")
#define CP_WAIT1()  asm volatile("cp.async.wait_group 1;" ::: "memory")
#define CP_WAIT0()  asm volatile("cp.async.wait_group 0;" ::: "memory")

__device__ __forceinline__ void ldsm4(uint32_t r[4], uint32_t a) {
    asm volatile("ldmatrix.sync.aligned.m8n8.x4.shared.b16 {%0,%1,%2,%3}, [%4];"
        : "=r"(r[0]), "=r"(r[1]), "=r"(r[2]), "=r"(r[3]) : "r"(a));
}
__device__ __forceinline__ void ldsm4t(uint32_t r[4], uint32_t a) {
    asm volatile("ldmatrix.sync.aligned.m8n8.x4.trans.shared.b16 {%0,%1,%2,%3}, [%4];"
        : "=r"(r[0]), "=r"(r[1]), "=r"(r[2]), "=r"(r[3]) : "r"(a));
}
__device__ __forceinline__ void mma16816(float c[4], const uint32_t a[4],
                                         uint32_t b0, uint32_t b1) {
    asm volatile("mma.sync.aligned.m16n8k16.row.col.f32.bf16.bf16.f32 "
        "{%0,%1,%2,%3}, {%4,%5,%6,%7}, {%8,%9}, {%0,%1,%2,%3};"
        : "+f"(c[0]), "+f"(c[1]), "+f"(c[2]), "+f"(c[3])
        : "r"(a[0]), "r"(a[1]), "r"(a[2]), "r"(a[3]), "r"(b0), "r"(b1));
}
__device__ __forceinline__ void split2(float v0, float v1, uint32_t& h, uint32_t& l) {
    __nv_bfloat162 hh = __floats2bfloat162_rn(v0, v1);
    float r0 = v0 - __bfloat162float(hh.x);
    float r1 = v1 - __bfloat162float(hh.y);
    __nv_bfloat162 ll = __floats2bfloat162_rn(r0, r1);
    h = *reinterpret_cast<uint32_t*>(&hh);
    l = *reinterpret_cast<uint32_t*>(&ll);
}
// [rows x 64] bf16 tile (128B rows), XOR swizzle: 8 chunks of 16B per row
#define SWZ(r, ch) (((r) << 7) | (((unsigned)((ch) ^ (r)) & 7u) << 4))
// [rows x 32] bf16 tile (64B rows): 4 chunks of 16B per row, conflict-free
// for 8-row ldmatrix groups: group(r,ch) = (r&1)*4 + (ch^((r>>1)&3)) distinct
#define SWZ32(r, ch) (((r) << 6) | (((unsigned)((ch) ^ (((r) >> 1) & 3)) & 3u) << 4))

// ---------------------------------------------------------------------------
__global__ __launch_bounds__(256)
void split_kernel(const float* __restrict__ src,
                  __nv_bfloat16* __restrict__ hi, __nv_bfloat16* __restrict__ lo) {
    size_t i = (size_t)blockIdx.x * 256 + threadIdx.x;
    float4 v = ((const float4*)src)[i];
    uint32_t h0, l0, h1, l1;
    split2(v.x, v.y, h0, l0);
    split2(v.z, v.w, h1, l1);
    ((uint32_t*)hi)[2*i+0] = h0;  ((uint32_t*)hi)[2*i+1] = h1;
    ((uint32_t*)lo)[2*i+0] = l0;  ((uint32_t*)lo)[2*i+1] = l1;
}

__global__ __launch_bounds__(256)
void tsplit4_kernel(const float* __restrict__ W0, const float* __restrict__ W1,
                    const float* __restrict__ W2, const float* __restrict__ W3,
                    __nv_bfloat16* __restrict__ ThB, __nv_bfloat16* __restrict__ TlB) {
    __shared__ float sm[32][33];
    const int tx = threadIdx.x, ty = threadIdx.y;
    const int n0 = blockIdx.x * 32, k0 = blockIdx.y * 32;
    const int z = blockIdx.z;
    const float* W = (z == 0) ? W0 : (z == 1 ? W1 : (z == 2 ? W2 : W3));
    __nv_bfloat16* Th = ThB + (size_t)z * EMB * EMB;
    __nv_bfloat16* Tl = TlB + (size_t)z * EMB * EMB;
#pragma unroll
    for (int r = ty; r < 32; r += 8)
        sm[r][tx] = W[(size_t)(k0 + r) * EMB + n0 + tx];
    __syncthreads();
#pragma unroll
    for (int r = ty; r < 32; r += 8) {
        float v = sm[tx][r];
        __nv_bfloat16 h = __float2bfloat16_rn(v);
        __nv_bfloat16 l = __float2bfloat16_rn(v - __bfloat162float(h));
        Th[(size_t)(n0 + r) * EMB + k0 + tx] = h;
        Tl[(size_t)(n0 + r) * EMB + k0 + tx] = l;
    }
}

// ---------------------------------------------------------------------------
// bf16x3 warp-MMA GEMM. K-chunk 32 -> stage 32KB, 3 stages = 96KB,
// occupancy 2 (16 warps/SM). Same mma sequence as the R6 WIN.
// Stage layout: Ah 0 | Al 8K | Bh 16K | Bl 24K (rows are 64B, SWZ32).
// ---------------------------------------------------------------------------
template<int HEADOUT>
__global__ __launch_bounds__(256, 2)
void gemm_mma(const __nv_bfloat16* __restrict__ Ah, const __nv_bfloat16* __restrict__ Al,
              const __nv_bfloat16* __restrict__ WhBase, const __nv_bfloat16* __restrict__ WlBase,
              const float* __restrict__ b0p, const float* __restrict__ b1p,
              const float* __restrict__ b2p, float* __restrict__ Co,
              __nv_bfloat16* __restrict__ C0h, __nv_bfloat16* __restrict__ C0l,
              __nv_bfloat16* __restrict__ C1h, __nv_bfloat16* __restrict__ C1l,
              __nv_bfloat16* __restrict__ C2h, __nv_bfloat16* __restrict__ C2l) {
    extern __shared__ __align__(128) char smem[];
    const uint32_t sb = smem_u32(smem);
    const int t = threadIdx.x, lane = t & 31, w = t >> 5;
    const int wm = (w & 3) * 32, wn = (w >> 2) * 64;
    const int m0 = blockIdx.y << 7, n0 = blockIdx.x << 7;
    const int z = HEADOUT ? blockIdx.z : 0;

    const __nv_bfloat16* Bh = WhBase + (size_t)z * EMB * EMB;
    const __nv_bfloat16* Bl = WlBase + (size_t)z * EMB * EMB;
    const float* bias = (z == 0) ? b0p : (z == 1 ? b1p : b2p);
    __nv_bfloat16* Ch = (z == 0) ? C0h : (z == 1 ? C1h : C2h);
    __nv_bfloat16* Cl = (z == 0) ? C0l : (z == 1 ? C1l : C2l);

    // issue one 32-wide K-chunk into stage st (8 cp16 per thread)
    auto issue = [&](int kb, int st) {
        const uint32_t s0 = sb + st * 32768;
        const int kc = kb << 5;
#pragma unroll
        for (int i = 0; i < 2; i++) {
            int idx = t + (i << 8);          // 0..511
            int row = idx >> 2, ch = idx & 3;
            int so = SWZ32(row, ch);
            size_t ga = (size_t)(m0 + row) * EMB + kc + (ch << 3);
            size_t gb = (size_t)(n0 + row) * EMB + kc + (ch << 3);
            cp16(s0 +         so, Ah + ga);
            cp16(s0 +  8192 + so, Al + ga);
            cp16(s0 + 16384 + so, Bh + gb);
            cp16(s0 + 24576 + so, Bl + gb);
        }
    };

    float c[2][8][4];
#pragma unroll
    for (int i = 0; i < 2; i++)
#pragma unroll
        for (int j = 0; j < 8; j++)
#pragma unroll
            for (int k = 0; k < 4; k++) c[i][j][k] = 0.f;

    issue(0, 0); CP_COMMIT();
    issue(1, 1); CP_COMMIT();

    for (int kb = 0; kb < 32; kb++) {
        CP_WAIT1();
        __syncthreads();
        if (kb + 2 < 32) issue(kb + 2, (kb + 2) % 3);
        CP_COMMIT();   // empty group near tail keeps wait_group accounting valid

        const uint32_t s0 = sb + (kb % 3) * 32768;
        const uint32_t sAh = s0, sAl = s0 + 8192, sBh = s0 + 16384, sBl = s0 + 24576;
#pragma unroll
        for (int s = 0; s < 2; s++) {
            const int ch = 2 * s + (lane >> 4);
            uint32_t ah[2][4], al[2][4];
#pragma unroll
            for (int mt = 0; mt < 2; mt++) {
                int r = wm + mt * 16 + (lane & 15);
                ldsm4(ah[mt], sAh + SWZ32(r, ch));
                ldsm4(al[mt], sAl + SWZ32(r, ch));
            }
#pragma unroll
            for (int g = 0; g < 4; g++) {
                int r = wn + g * 16 + (lane & 15);
                uint32_t bh[4], bl[4];
                ldsm4(bh, sBh + SWZ32(r, ch));
                ldsm4(bl, sBl + SWZ32(r, ch));
#pragma unroll
                for (int mt = 0; mt < 2; mt++) {
                    mma16816(c[mt][2*g],   ah[mt], bh[0], bh[2]);
                    mma16816(c[mt][2*g+1], ah[mt], bh[1], bh[3]);
                    mma16816(c[mt][2*g],   ah[mt], bl[0], bl[2]);
                    mma16816(c[mt][2*g+1], ah[mt], bl[1], bl[3]);
                    mma16816(c[mt][2*g],   al[mt], bh[0], bh[2]);
                    mma16816(c[mt][2*g+1], al[mt], bh[1], bh[3]);
                }
            }
        }
    }

#pragma unroll
    for (int mt = 0; mt < 2; mt++) {
#pragma unroll
        for (int nt = 0; nt < 8; nt++) {
            const int col = n0 + wn + nt * 8 + ((lane & 3) << 1);
            const float b0 = bias[col], b1 = bias[col + 1];
            const int r0 = m0 + wm + mt * 16 + (lane >> 2);
#pragma unroll
            for (int half = 0; half < 2; half++) {
                const int r = r0 + half * 8;
                const float v0 = c[mt][nt][half*2+0] + b0;
                const float v1 = c[mt][nt][half*2+1] + b1;
                if (HEADOUT) {
                    uint32_t h2, l2;
                    split2(v0, v1, h2, l2);
                    const int bb = r >> 11, srow = r & 2047;
                    const int hd = col >> 6, d = col & 63;
                    const size_t off = (((size_t)(bb * NH + hd)) * SEQ + srow) * HD + d;
                    *(uint32_t*)(Ch + off) = h2;
                    *(uint32_t*)(Cl + off) = l2;
                } else {
                    *(float2*)(Co + (size_t)r * EMB + col) = make_float2(v0, v1);
                }
            }
        }
    }
}

// ---------------------------------------------------------------------------
// Flash attention — exact R6 WIN version (128-query block, 8 warps x m16,
// 2-stage cp.async K/V pipeline, occ 2).
// smem: Q 32KB | KV stage0 32KB | KV stage1 32KB | mask bias 8KB = 104KB.
// ---------------------------------------------------------------------------
__global__ __launch_bounds__(256, 2)
void attn_mma(const int* __restrict__ mask) {
    extern __shared__ __align__(128) char smem[];
    char* pQh = smem;
    char* pQl = smem + 16384;
    const uint32_t sQh = smem_u32(pQh), sQl = smem_u32(pQl);
    const uint32_t sKV = smem_u32(smem + 32768);
    float* smb = (float*)(smem + 98304);

    const int t = threadIdx.x, lane = t & 31, w = t >> 5;
    const int qb = blockIdx.x, h = blockIdx.y, b = blockIdx.z;
    const size_t base = ((size_t)(b * NH + h)) * SEQ * HD;

    auto issue_kv = [&](int kb, int st) {
        const uint32_t s0 = sKV + st * 32768;
#pragma unroll
        for (int i = 0; i < 2; i++) {
            int idx = t + (i << 8);
            int row = idx >> 3, ch = idx & 7;
            int so = SWZ(row, ch);
            size_t ga = base + (size_t)(kb * 64 + row) * HD + (ch << 3);
            cp16(s0 +         so, g_Kh + ga);
            cp16(s0 +  8192 + so, g_Kl + ga);
            cp16(s0 + 16384 + so, g_Vh + ga);
            cp16(s0 + 24576 + so, g_Vl + ga);
        }
    };

#pragma unroll
    for (int i = 0; i < 4; i++) {
        int idx = t + (i << 8);
        int row = idx >> 3, ch = idx & 7;
        int so = SWZ(row, ch);
        size_t ga = base + (size_t)(qb * 128 + row) * HD + (ch << 3);
        cp16(sQh + so, g_Qh + ga);
        cp16(sQl + so, g_Ql + ga);
    }
    {
        const int4* m4 = (const int4*)(mask + b * SEQ);
#pragma unroll
        for (int i = 0; i < 2; i++) {
            int idx = t + (i << 8);
            int4 mm = m4[idx];
            smb[idx*4+0] = mm.x ? 0.f : -1.0e9f;
            smb[idx*4+1] = mm.y ? 0.f : -1.0e9f;
            smb[idx*4+2] = mm.z ? 0.f : -1.0e9f;
            smb[idx*4+3] = mm.w ? 0.f : -1.0e9f;
        }
    }
    issue_kv(0, 0); CP_COMMIT();

    float o[8][4];
#pragma unroll
    for (int i = 0; i < 8; i++)
#pragma unroll
        for (int j = 0; j < 4; j++) o[i][j] = 0.f;
    float mrow[2] = {-INFINITY, -INFINITY};
    float lsum[2] = {0.f, 0.f};

    for (int kb = 0; kb < SEQ / 64; kb++) {
        CP_WAIT0();
        __syncthreads();
        if (kb + 1 < SEQ / 64) issue_kv(kb + 1, (kb + 1) & 1);
        CP_COMMIT();

        const uint32_t s0 = sKV + (kb & 1) * 32768;
        const uint32_t sKh = s0, sKl = s0 + 8192, sVh = s0 + 16384, sVl = s0 + 24576;

        float c[8][4];
#pragma unroll
        for (int i = 0; i < 8; i++)
#pragma unroll
            for (int j = 0; j < 4; j++) c[i][j] = 0.f;
#pragma unroll
        for (int s = 0; s < 4; s++) {
            const int ch = 2 * s + (lane >> 4);
            uint32_t ah[4], al[4];
            const int rq = w * 16 + (lane & 15);
            ldsm4(ah, sQh + SWZ(rq, ch));
            ldsm4(al, sQl + SWZ(rq, ch));
#pragma unroll
            for (int g = 0; g < 4; g++) {
                const int rk = g * 16 + (lane & 15);
                uint32_t bh[4], bl[4];
                ldsm4(bh, sKh + SWZ(rk, ch));
                ldsm4(bl, sKl + SWZ(rk, ch));
                mma16816(c[2*g],   ah, bh[0], bh[2]);
                mma16816(c[2*g+1], ah, bh[1], bh[3]);
                mma16816(c[2*g],   ah, bl[0], bl[2]);
                mma16816(c[2*g+1], ah, bl[1], bl[3]);
                mma16816(c[2*g],   al, bh[0], bh[2]);
                mma16816(c[2*g+1], al, bh[1], bh[3]);
            }
        }

        const int cb = (lane & 3) << 1;
        const float* mbt = smb + kb * 64;
#pragma unroll
        for (int nt = 0; nt < 8; nt++) {
            const float m0v = mbt[nt * 8 + cb], m1v = mbt[nt * 8 + cb + 1];
            c[nt][0] = fmaf(c[nt][0], 0.125f, m0v);
            c[nt][1] = fmaf(c[nt][1], 0.125f, m1v);
            c[nt][2] = fmaf(c[nt][2], 0.125f, m0v);
            c[nt][3] = fmaf(c[nt][3], 0.125f, m1v);
        }

        float mxA = -INFINITY, mxB = -INFINITY;
#pragma unroll
        for (int nt = 0; nt < 8; nt++) {
            mxA = fmaxf(mxA, fmaxf(c[nt][0], c[nt][1]));
            mxB = fmaxf(mxB, fmaxf(c[nt][2], c[nt][3]));
        }
#pragma unroll
        for (int off = 1; off < 4; off <<= 1) {
            mxA = fmaxf(mxA, __shfl_xor_sync(0xffffffffu, mxA, off));
            mxB = fmaxf(mxB, __shfl_xor_sync(0xffffffffu, mxB, off));
        }
        const float nmA = fmaxf(mrow[0], mxA), nmB = fmaxf(mrow[1], mxB);
        const float scA = __expf(mrow[0] - nmA), scB = __expf(mrow[1] - nmB);
        mrow[0] = nmA; mrow[1] = nmB;
        float sA = 0.f, sB = 0.f;
#pragma unroll
        for (int nt = 0; nt < 8; nt++) {
            c[nt][0] = __expf(c[nt][0] - nmA);
            c[nt][1] = __expf(c[nt][1] - nmA);
            c[nt][2] = __expf(c[nt][2] - nmB);
            c[nt][3] = __expf(c[nt][3] - nmB);
            sA += c[nt][0] + c[nt][1];
            sB += c[nt][2] + c[nt][3];
        }
#pragma unroll
        for (int off = 1; off < 4; off <<= 1) {
            sA += __shfl_xor_sync(0xffffffffu, sA, off);
            sB += __shfl_xor_sync(0xffffffffu, sB, off);
        }
        lsum[0] = lsum[0] * scA + sA;
        lsum[1] = lsum[1] * scB + sB;
#pragma unroll
        for (int nt = 0; nt < 8; nt++) {
            o[nt][0] *= scA; o[nt][1] *= scA;
            o[nt][2] *= scB; o[nt][3] *= scB;
        }

#pragma unroll
        for (int kt = 0; kt < 4; kt++) {
            uint32_t ph[4], pl[4];
            split2(c[2*kt][0],   c[2*kt][1],   ph[0], pl[0]);
            split2(c[2*kt][2],   c[2*kt][3],   ph[1], pl[1]);
            split2(c[2*kt+1][0], c[2*kt+1][1], ph[2], pl[2]);
            split2(c[2*kt+1][2], c[2*kt+1][3], ph[3], pl[3]);
            const int rv = kt * 16 + (lane & 15);
#pragma unroll
            for (int g = 0; g < 4; g++) {
                const int chv = 2 * g + (lane >> 4);
                uint32_t vh[4], vl[4];
                ldsm4t(vh, sVh + SWZ(rv, chv));
                ldsm4t(vl, sVl + SWZ(rv, chv));
                mma16816(o[2*g],   ph, vh[0], vh[1]);
                mma16816(o[2*g+1], ph, vh[2], vh[3]);
                mma16816(o[2*g],   ph, vl[0], vl[1]);
                mma16816(o[2*g+1], ph, vl[2], vl[3]);
                mma16816(o[2*g],   pl, vh[0], vh[1]);
                mma16816(o[2*g+1], pl, vh[2], vh[3]);
            }
        }
    }

    const float iA = 1.f / lsum[0], iB = 1.f / lsum[1];
    const int rA = qb * 128 + w * 16 + (lane >> 2);
    const int colb = (lane & 3) << 1;
#pragma unroll
    for (int nt = 0; nt < 8; nt++) {
        const int col = h * HD + nt * 8 + colb;
        uint32_t h2, l2;
        split2(o[nt][0] * iA, o[nt][1] * iA, h2, l2);
        size_t off = ((size_t)b * SEQ + rA) * EMB + col;
        *(uint32_t*)(g_xh + off) = h2;
        *(uint32_t*)(g_xl + off) = l2;
        split2(o[nt][2] * iB, o[nt][3] * iB, h2, l2);
        off = ((size_t)b * SEQ + rA + 8) * EMB + col;
        *(uint32_t*)(g_xh + off) = h2;
        *(uint32_t*)(g_xl + off) = l2;
    }
}

// ---------------------------------------------------------------------------
extern "C" void kernel_launch(void* const* d_in, const int* in_sizes, int n_in,
                              void* d_out, int out_size) {
    const float* x  = (const float*)d_in[0];
    const int*  mask = (const int*)d_in[1];
    const float* Wq = (const float*)d_in[2];
    const float* bq = (const float*)d_in[3];
    const float* Wk = (const float*)d_in[4];
    const float* bk = (const float*)d_in[5];
    const float* Wv = (const float*)d_in[6];
    const float* bv = (const float*)d_in[7];
    const float* Wo = (const float*)d_in[8];
    const float* bo = (const float*)d_in[9];

    __nv_bfloat16 *xh, *xl, *wh, *wl, *Qh, *Ql, *Kh, *Kl, *Vh, *Vl;
    cudaGetSymbolAddress((void**)&xh, g_xh);
    cudaGetSymbolAddress((void**)&xl, g_xl);
    cudaGetSymbolAddress((void**)&wh, g_wh);
    cudaGetSymbolAddress((void**)&wl, g_wl);
    cudaGetSymbolAddress((void**)&Qh, g_Qh);
    cudaGetSymbolAddress((void**)&Ql, g_Ql);
    cudaGetSymbolAddress((void**)&Kh, g_Kh);
    cudaGetSymbolAddress((void**)&Kl, g_Kl);
    cudaGetSymbolAddress((void**)&Vh, g_Vh);
    cudaGetSymbolAddress((void**)&Vl, g_Vl);
    const size_t WS = (size_t)EMB * EMB;

    const int GEMM_SMEM = 3 * 32768;           // 96KB -> occupancy 2
    const int ATTN_SMEM = 98304 + 8192;        // 104KB -> occupancy 2
    cudaFuncSetAttribute(gemm_mma<1>, cudaFuncAttributeMaxDynamicSharedMemorySize, GEMM_SMEM);
    cudaFuncSetAttribute(gemm_mma<0>, cudaFuncAttributeMaxDynamicSharedMemorySize, GEMM_SMEM);
    cudaFuncSetAttribute(attn_mma,    cudaFuncAttributeMaxDynamicSharedMemorySize, ATTN_SMEM);

    // input split + all 4 weight transpose/splits in one launch
    split_kernel<<<(MTOT*EMB)/4/256, 256>>>(x, xh, xl);
    tsplit4_kernel<<<dim3(32,32,4), dim3(32,8)>>>(Wq, Wk, Wv, Wo, wh, wl);

    // fused QKV projection (z = 0,1,2 -> Q,K,V), bf16 hi/lo out in [B,H,S,D]
    gemm_mma<1><<<dim3(EMB/128, MTOT/128, 3), 256, GEMM_SMEM>>>(
        xh, xl, wh, wl, bq, bk, bv, nullptr, Qh, Ql, Kh, Kl, Vh, Vl);

    // attention (128-query blocks, occ 2) -> bf16 hi/lo activations into xh/xl
    attn_mma<<<dim3(SEQ/128, NH, BSZ), 256, ATTN_SMEM>>>(mask);

    // O projection -> fp32 d_out
    gemm_mma<0><<<dim3(EMB/128, MTOT/128, 1), 256, GEMM_SMEM>>>(
        xh, xl, wh + 3*WS, wl + 3*WS, bo, bo, bo, (float*)d_out,
        nullptr, nullptr, nullptr, nullptr, nullptr, nullptr);
}

// round 10
// speedup vs baseline: 1.3673x; 1.2540x over previous
#include <cuda_runtime.h>
#include <cuda_bf16.h>
#include <math.h>
#include <stdint.h>

#define BSZ 4
#define SEQ 2048
#define EMB 1024
#define NH 16
#define HD 64
#define MTOT (BSZ*SEQ)   // 8192

// ---------------- scratch (__device__ globals; no allocs allowed) ----------
static __device__ __align__(256) __nv_bfloat16 g_xh[(size_t)MTOT*EMB];
static __device__ __align__(256) __nv_bfloat16 g_xl[(size_t)MTOT*EMB];
static __device__ __align__(256) __nv_bfloat16 g_wh[4][(size_t)EMB*EMB];
static __device__ __align__(256) __nv_bfloat16 g_wl[4][(size_t)EMB*EMB];
static __device__ __align__(256) __nv_bfloat16 g_Qh[(size_t)MTOT*EMB];
static __device__ __align__(256) __nv_bfloat16 g_Ql[(size_t)MTOT*EMB];
static __device__ __align__(256) __nv_bfloat16 g_Kh[(size_t)MTOT*EMB];
static __device__ __align__(256) __nv_bfloat16 g_Kl[(size_t)MTOT*EMB];
static __device__ __align__(256) __nv_bfloat16 g_Vh[(size_t)MTOT*EMB];
static __device__ __align__(256) __nv_bfloat16 g_Vl[(size_t)MTOT*EMB];
// mask-compacted K/V (zero-initialized; pad rows stay zero forever)
static __device__ __align__(256) __nv_bfloat16 g_cKh[(size_t)MTOT*EMB];
static __device__ __align__(256) __nv_bfloat16 g_cKl[(size_t)MTOT*EMB];
static __device__ __align__(256) __nv_bfloat16 g_cVh[(size_t)MTOT*EMB];
static __device__ __align__(256) __nv_bfloat16 g_cVl[(size_t)MTOT*EMB];
static __device__ int g_cnt[BSZ];
static __device__ int g_idx[BSZ*SEQ];

// ---------------- helpers --------------------------------------------------
__device__ __forceinline__ uint32_t smem_u32(const void* p) {
    uint32_t a;
    asm("{ .reg .u64 t; cvta.to.shared.u64 t, %1; cvt.u32.u64 %0, t; }"
        : "=r"(a) : "l"(p));
    return a;
}
__device__ __forceinline__ void cp16(uint32_t dst, const void* src) {
    asm volatile("cp.async.cg.shared.global [%0], [%1], 16;" :: "r"(dst), "l"(src));
}
#define CP_COMMIT() asm volatile("cp.async.commit_group;" ::: "memory")
#define CP_WAIT1()  asm volatile("cp.async.wait_group 1;" ::: "memory")
#define CP_WAIT0()  asm volatile("cp.async.wait_group 0;" ::: "memory")

__device__ __forceinline__ void ldsm4(uint32_t r[4], uint32_t a) {
    asm volatile("ldmatrix.sync.aligned.m8n8.x4.shared.b16 {%0,%1,%2,%3}, [%4];"
        : "=r"(r[0]), "=r"(r[1]), "=r"(r[2]), "=r"(r[3]) : "r"(a));
}
__device__ __forceinline__ void ldsm4t(uint32_t r[4], uint32_t a) {
    asm volatile("ldmatrix.sync.aligned.m8n8.x4.trans.shared.b16 {%0,%1,%2,%3}, [%4];"
        : "=r"(r[0]), "=r"(r[1]), "=r"(r[2]), "=r"(r[3]) : "r"(a));
}
__device__ __forceinline__ void mma16816(float c[4], const uint32_t a[4],
                                         uint32_t b0, uint32_t b1) {
    asm volatile("mma.sync.aligned.m16n8k16.row.col.f32.bf16.bf16.f32 "
        "{%0,%1,%2,%3}, {%4,%5,%6,%7}, {%8,%9}, {%0,%1,%2,%3};"
        : "+f"(c[0]), "+f"(c[1]), "+f"(c[2]), "+f"(c[3])
        : "r"(a[0]), "r"(a[1]), "r"(a[2]), "r"(a[3]), "r"(b0), "r"(b1));
}
__device__ __forceinline__ void split2(float v0, float v1, uint32_t& h, uint32_t& l) {
    __nv_bfloat162 hh = __floats2bfloat162_rn(v0, v1);
    float r0 = v0 - __bfloat162float(hh.x);
    float r1 = v1 - __bfloat162float(hh.y);
    __nv_bfloat162 ll = __floats2bfloat162_rn(r0, r1);
    h = *reinterpret_cast<uint32_t*>(&hh);
    l = *reinterpret_cast<uint32_t*>(&ll);
}
// [rows x 64] bf16 tile (128B rows), XOR swizzle: 8 chunks of 16B per row
#define SWZ(r, ch) (((r) << 7) | (((unsigned)((ch) ^ (r)) & 7u) << 4))
// [rows x 32] bf16 tile (64B rows): conflict-free for 8-row ldmatrix groups
#define SWZ32(r, ch) (((r) << 6) | (((unsigned)((ch) ^ (((r) >> 1) & 3)) & 3u) << 4))

// ---------------------------------------------------------------------------
__global__ __launch_bounds__(256)
void split_kernel(const float* __restrict__ src,
                  __nv_bfloat16* __restrict__ hi, __nv_bfloat16* __restrict__ lo) {
    size_t i = (size_t)blockIdx.x * 256 + threadIdx.x;
    float4 v = ((const float4*)src)[i];
    uint32_t h0, l0, h1, l1;
    split2(v.x, v.y, h0, l0);
    split2(v.z, v.w, h1, l1);
    ((uint32_t*)hi)[2*i+0] = h0;  ((uint32_t*)hi)[2*i+1] = h1;
    ((uint32_t*)lo)[2*i+0] = l0;  ((uint32_t*)lo)[2*i+1] = l1;
}

__global__ __launch_bounds__(256)
void tsplit4_kernel(const float* __restrict__ W0, const float* __restrict__ W1,
                    const float* __restrict__ W2, const float* __restrict__ W3,
                    __nv_bfloat16* __restrict__ ThB, __nv_bfloat16* __restrict__ TlB) {
    __shared__ float sm[32][33];
    const int tx = threadIdx.x, ty = threadIdx.y;
    const int n0 = blockIdx.x * 32, k0 = blockIdx.y * 32;
    const int z = blockIdx.z;
    const float* W = (z == 0) ? W0 : (z == 1 ? W1 : (z == 2 ? W2 : W3));
    __nv_bfloat16* Th = ThB + (size_t)z * EMB * EMB;
    __nv_bfloat16* Tl = TlB + (size_t)z * EMB * EMB;
#pragma unroll
    for (int r = ty; r < 32; r += 8)
        sm[r][tx] = W[(size_t)(k0 + r) * EMB + n0 + tx];
    __syncthreads();
#pragma unroll
    for (int r = ty; r < 32; r += 8) {
        float v = sm[tx][r];
        __nv_bfloat16 h = __float2bfloat16_rn(v);
        __nv_bfloat16 l = __float2bfloat16_rn(v - __bfloat162float(h));
        Th[(size_t)(n0 + r) * EMB + k0 + tx] = h;
        Tl[(size_t)(n0 + r) * EMB + k0 + tx] = l;
    }
}

// ---------------------------------------------------------------------------
// per-batch compaction: indices of unmasked keys (order-preserving) + count
// ---------------------------------------------------------------------------
__global__ __launch_bounds__(256)
void compact_kernel(const int* __restrict__ mask) {
    __shared__ int woff[8];
    const int b = blockIdx.x, t = threadIdx.x, lane = t & 31, w = t >> 5;
    const int* m = mask + b * SEQ;
    int v[8], cnt = 0;
#pragma unroll
    for (int i = 0; i < 8; i++) { v[i] = m[t * 8 + i]; cnt += (v[i] != 0); }
    int inc = cnt;
#pragma unroll
    for (int off = 1; off < 32; off <<= 1) {
        int nv = __shfl_up_sync(0xffffffffu, inc, off);
        if (lane >= off) inc += nv;
    }
    if (lane == 31) woff[w] = inc;
    __syncthreads();
    if (t == 0) {
        int run = 0;
#pragma unroll
        for (int j = 0; j < 8; j++) { int tmp = woff[j]; woff[j] = run; run += tmp; }
        g_cnt[b] = run;
    }
    __syncthreads();
    int off = woff[w] + inc - cnt;   // exclusive prefix for this thread
#pragma unroll
    for (int i = 0; i < 8; i++)
        if (v[i]) g_idx[b * SEQ + off++] = t * 8 + i;
}

// gather unmasked K/V rows into compacted buffers (pad rows stay zero)
__global__ __launch_bounds__(256)
void gather_kernel() {
    const int b = blockIdx.z, h = blockIdx.y;
    const int n = g_cnt[b];
    const int j = blockIdx.x * 32 + (threadIdx.x >> 3);
    if (j >= n) return;
    const int c = (threadIdx.x & 7) << 3;
    const int src = g_idx[b * SEQ + j];
    const size_t sb_ = (((size_t)(b * NH + h)) * SEQ + src) * HD + c;
    const size_t db_ = (((size_t)(b * NH + h)) * SEQ + j) * HD + c;
    *(uint4*)(g_cKh + db_) = *(const uint4*)(g_Kh + sb_);
    *(uint4*)(g_cKl + db_) = *(const uint4*)(g_Kl + sb_);
    *(uint4*)(g_cVh + db_) = *(const uint4*)(g_Vh + sb_);
    *(uint4*)(g_cVl + db_) = *(const uint4*)(g_Vl + sb_);
}

// ---------------------------------------------------------------------------
// bf16x3 warp-MMA GEMM (R9 WIN, unchanged). K-chunk 32, 3 stages, occ 2.
// ---------------------------------------------------------------------------
template<int HEADOUT>
__global__ __launch_bounds__(256, 2)
void gemm_mma(const __nv_bfloat16* __restrict__ Ah, const __nv_bfloat16* __restrict__ Al,
              const __nv_bfloat16* __restrict__ WhBase, const __nv_bfloat16* __restrict__ WlBase,
              const float* __restrict__ b0p, const float* __restrict__ b1p,
              const float* __restrict__ b2p, float* __restrict__ Co,
              __nv_bfloat16* __restrict__ C0h, __nv_bfloat16* __restrict__ C0l,
              __nv_bfloat16* __restrict__ C1h, __nv_bfloat16* __restrict__ C1l,
              __nv_bfloat16* __restrict__ C2h, __nv_bfloat16* __restrict__ C2l) {
    extern __shared__ __align__(128) char smem[];
    const uint32_t sb = smem_u32(smem);
    const int t = threadIdx.x, lane = t & 31, w = t >> 5;
    const int wm = (w & 3) * 32, wn = (w >> 2) * 64;
    const int m0 = blockIdx.y << 7, n0 = blockIdx.x << 7;
    const int z = HEADOUT ? blockIdx.z : 0;

    const __nv_bfloat16* Bh = WhBase + (size_t)z * EMB * EMB;
    const __nv_bfloat16* Bl = WlBase + (size_t)z * EMB * EMB;
    const float* bias = (z == 0) ? b0p : (z == 1 ? b1p : b2p);
    __nv_bfloat16* Ch = (z == 0) ? C0h : (z == 1 ? C1h : C2h);
    __nv_bfloat16* Cl = (z == 0) ? C0l : (z == 1 ? C1l : C2l);

    auto issue = [&](int kb, int st) {
        const uint32_t s0 = sb + st * 32768;
        const int kc = kb << 5;
#pragma unroll
        for (int i = 0; i < 2; i++) {
            int idx = t + (i << 8);
            int row = idx >> 2, ch = idx & 3;
            int so = SWZ32(row, ch);
            size_t ga = (size_t)(m0 + row) * EMB + kc + (ch << 3);
            size_t gb = (size_t)(n0 + row) * EMB + kc + (ch << 3);
            cp16(s0 +         so, Ah + ga);
            cp16(s0 +  8192 + so, Al + ga);
            cp16(s0 + 16384 + so, Bh + gb);
            cp16(s0 + 24576 + so, Bl + gb);
        }
    };

    float c[2][8][4];
#pragma unroll
    for (int i = 0; i < 2; i++)
#pragma unroll
        for (int j = 0; j < 8; j++)
#pragma unroll
            for (int k = 0; k < 4; k++) c[i][j][k] = 0.f;

    issue(0, 0); CP_COMMIT();
    issue(1, 1); CP_COMMIT();

    for (int kb = 0; kb < 32; kb++) {
        CP_WAIT1();
        __syncthreads();
        if (kb + 2 < 32) issue(kb + 2, (kb + 2) % 3);
        CP_COMMIT();

        const uint32_t s0 = sb + (kb % 3) * 32768;
        const uint32_t sAh = s0, sAl = s0 + 8192, sBh = s0 + 16384, sBl = s0 + 24576;
#pragma unroll
        for (int s = 0; s < 2; s++) {
            const int ch = 2 * s + (lane >> 4);
            uint32_t ah[2][4], al[2][4];
#pragma unroll
            for (int mt = 0; mt < 2; mt++) {
                int r = wm + mt * 16 + (lane & 15);
                ldsm4(ah[mt], sAh + SWZ32(r, ch));
                ldsm4(al[mt], sAl + SWZ32(r, ch));
            }
#pragma unroll
            for (int g = 0; g < 4; g++) {
                int r = wn + g * 16 + (lane & 15);
                uint32_t bh[4], bl[4];
                ldsm4(bh, sBh + SWZ32(r, ch));
                ldsm4(bl, sBl + SWZ32(r, ch));
#pragma unroll
                for (int mt = 0; mt < 2; mt++) {
                    mma16816(c[mt][2*g],   ah[mt], bh[0], bh[2]);
                    mma16816(c[mt][2*g+1], ah[mt], bh[1], bh[3]);
                    mma16816(c[mt][2*g],   ah[mt], bl[0], bl[2]);
                    mma16816(c[mt][2*g+1], ah[mt], bl[1], bl[3]);
                    mma16816(c[mt][2*g],   al[mt], bh[0], bh[2]);
                    mma16816(c[mt][2*g+1], al[mt], bh[1], bh[3]);
                }
            }
        }
    }

#pragma unroll
    for (int mt = 0; mt < 2; mt++) {
#pragma unroll
        for (int nt = 0; nt < 8; nt++) {
            const int col = n0 + wn + nt * 8 + ((lane & 3) << 1);
            const float b0 = bias[col], b1 = bias[col + 1];
            const int r0 = m0 + wm + mt * 16 + (lane >> 2);
#pragma unroll
            for (int half = 0; half < 2; half++) {
                const int r = r0 + half * 8;
                const float v0 = c[mt][nt][half*2+0] + b0;
                const float v1 = c[mt][nt][half*2+1] + b1;
                if (HEADOUT) {
                    uint32_t h2, l2;
                    split2(v0, v1, h2, l2);
                    const int bb = r >> 11, srow = r & 2047;
                    const int hd = col >> 6, d = col & 63;
                    const size_t off = (((size_t)(bb * NH + hd)) * SEQ + srow) * HD + d;
                    *(uint32_t*)(Ch + off) = h2;
                    *(uint32_t*)(Cl + off) = l2;
                } else {
                    *(float2*)(Co + (size_t)r * EMB + col) = make_float2(v0, v1);
                }
            }
        }
    }
}

// ---------------------------------------------------------------------------
// Flash attention over COMPACTED K/V: loop only over ceil(n_b/64) tiles.
// Mask bias replaced by (col < n) select; pad columns -> weight exactly 0.
// smem: Q 32KB | KV stage0 32KB | KV stage1 32KB = 96KB, occ 2.
// ---------------------------------------------------------------------------
__global__ __launch_bounds__(256, 2)
void attn_mma() {
    extern __shared__ __align__(128) char smem[];
    char* pQh = smem;
    char* pQl = smem + 16384;
    const uint32_t sQh = smem_u32(pQh), sQl = smem_u32(pQl);
    const uint32_t sKV = smem_u32(smem + 32768);

    const int t = threadIdx.x, lane = t & 31, w = t >> 5;
    const int qb = blockIdx.x, h = blockIdx.y, b = blockIdx.z;
    const size_t base = ((size_t)(b * NH + h)) * SEQ * HD;
    const int n = g_cnt[b];
    const int ntiles = (n + 63) >> 6;

    auto issue_kv = [&](int kb, int st) {
        const uint32_t s0 = sKV + st * 32768;
#pragma unroll
        for (int i = 0; i < 2; i++) {
            int idx = t + (i << 8);
            int row = idx >> 3, ch = idx & 7;
            int so = SWZ(row, ch);
            size_t ga = base + (size_t)(kb * 64 + row) * HD + (ch << 3);
            cp16(s0 +         so, g_cKh + ga);
            cp16(s0 +  8192 + so, g_cKl + ga);
            cp16(s0 + 16384 + so, g_cVh + ga);
            cp16(s0 + 24576 + so, g_cVl + ga);
        }
    };

#pragma unroll
    for (int i = 0; i < 4; i++) {
        int idx = t + (i << 8);
        int row = idx >> 3, ch = idx & 7;
        int so = SWZ(row, ch);
        size_t ga = base + (size_t)(qb * 128 + row) * HD + (ch << 3);
        cp16(sQh + so, g_Qh + ga);
        cp16(sQl + so, g_Ql + ga);
    }
    issue_kv(0, 0); CP_COMMIT();

    float o[8][4];
#pragma unroll
    for (int i = 0; i < 8; i++)
#pragma unroll
        for (int j = 0; j < 4; j++) o[i][j] = 0.f;
    float mrow[2] = {-INFINITY, -INFINITY};
    float lsum[2] = {0.f, 0.f};

    for (int kb = 0; kb < ntiles; kb++) {
        CP_WAIT0();
        __syncthreads();
        if (kb + 1 < ntiles) issue_kv(kb + 1, (kb + 1) & 1);
        CP_COMMIT();

        const uint32_t s0 = sKV + (kb & 1) * 32768;
        const uint32_t sKh = s0, sKl = s0 + 8192, sVh = s0 + 16384, sVl = s0 + 24576;

        float c[8][4];
#pragma unroll
        for (int i = 0; i < 8; i++)
#pragma unroll
            for (int j = 0; j < 4; j++) c[i][j] = 0.f;
#pragma unroll
        for (int s = 0; s < 4; s++) {
            const int ch = 2 * s + (lane >> 4);
            uint32_t ah[4], al[4];
            const int rq = w * 16 + (lane & 15);
            ldsm4(ah, sQh + SWZ(rq, ch));
            ldsm4(al, sQl + SWZ(rq, ch));
#pragma unroll
            for (int g = 0; g < 4; g++) {
                const int rk = g * 16 + (lane & 15);
                uint32_t bh[4], bl[4];
                ldsm4(bh, sKh + SWZ(rk, ch));
                ldsm4(bl, sKl + SWZ(rk, ch));
                mma16816(c[2*g],   ah, bh[0], bh[2]);
                mma16816(c[2*g+1], ah, bh[1], bh[3]);
                mma16816(c[2*g],   ah, bl[0], bl[2]);
                mma16816(c[2*g+1], ah, bl[1], bl[3]);
                mma16816(c[2*g],   al, bh[0], bh[2]);
                mma16816(c[2*g+1], al, bh[1], bh[3]);
            }
        }

        // scale + validity select (pad cols -> exactly -1e9 -> weight 0)
        const int cb = (lane & 3) << 1;
#pragma unroll
        for (int nt = 0; nt < 8; nt++) {
            const int col = kb * 64 + nt * 8 + cb;
            const bool v0 = col < n, v1 = col + 1 < n;
            c[nt][0] = v0 ? c[nt][0] * 0.125f : -1.0e9f;
            c[nt][1] = v1 ? c[nt][1] * 0.125f : -1.0e9f;
            c[nt][2] = v0 ? c[nt][2] * 0.125f : -1.0e9f;
            c[nt][3] = v1 ? c[nt][3] * 0.125f : -1.0e9f;
        }

        float mxA = -INFINITY, mxB = -INFINITY;
#pragma unroll
        for (int nt = 0; nt < 8; nt++) {
            mxA = fmaxf(mxA, fmaxf(c[nt][0], c[nt][1]));
            mxB = fmaxf(mxB, fmaxf(c[nt][2], c[nt][3]));
        }
#pragma unroll
        for (int off = 1; off < 4; off <<= 1) {
            mxA = fmaxf(mxA, __shfl_xor_sync(0xffffffffu, mxA, off));
            mxB = fmaxf(mxB, __shfl_xor_sync(0xffffffffu, mxB, off));
        }
        const float nmA = fmaxf(mrow[0], mxA), nmB = fmaxf(mrow[1], mxB);
        const float scA = __expf(mrow[0] - nmA), scB = __expf(mrow[1] - nmB);
        mrow[0] = nmA; mrow[1] = nmB;
        float sA = 0.f, sB = 0.f;
#pragma unroll
        for (int nt = 0; nt < 8; nt++) {
            c[nt][0] = __expf(c[nt][0] - nmA);
            c[nt][1] = __expf(c[nt][1] - nmA);
            c[nt][2] = __expf(c[nt][2] - nmB);
            c[nt][3] = __expf(c[nt][3] - nmB);
            sA += c[nt][0] + c[nt][1];
            sB += c[nt][2] + c[nt][3];
        }
#pragma unroll
        for (int off = 1; off < 4; off <<= 1) {
            sA += __shfl_xor_sync(0xffffffffu, sA, off);
            sB += __shfl_xor_sync(0xffffffffu, sB, off);
        }
        lsum[0] = lsum[0] * scA + sA;
        lsum[1] = lsum[1] * scB + sB;
#pragma unroll
        for (int nt = 0; nt < 8; nt++) {
            o[nt][0] *= scA; o[nt][1] *= scA;
            o[nt][2] *= scB; o[nt][3] *= scB;
        }

#pragma unroll
        for (int kt = 0; kt < 4; kt++) {
            uint32_t ph[4], pl[4];
            split2(c[2*kt][0],   c[2*kt][1],   ph[0], pl[0]);
            split2(c[2*kt][2],   c[2*kt][3],   ph[1], pl[1]);
            split2(c[2*kt+1][0], c[2*kt+1][1], ph[2], pl[2]);
            split2(c[2*kt+1][2], c[2*kt+1][3], ph[3], pl[3]);
            const int rv = kt * 16 + (lane & 15);
#pragma unroll
            for (int g = 0; g < 4; g++) {
                const int chv = 2 * g + (lane >> 4);
                uint32_t vh[4], vl[4];
                ldsm4t(vh, sVh + SWZ(rv, chv));
                ldsm4t(vl, sVl + SWZ(rv, chv));
                mma16816(o[2*g],   ph, vh[0], vh[1]);
                mma16816(o[2*g+1], ph, vh[2], vh[3]);
                mma16816(o[2*g],   ph, vl[0], vl[1]);
                mma16816(o[2*g+1], ph, vl[2], vl[3]);
                mma16816(o[2*g],   pl, vh[0], vh[1]);
                mma16816(o[2*g+1], pl, vh[2], vh[3]);
            }
        }
    }

    const float iA = 1.f / lsum[0], iB = 1.f / lsum[1];
    const int rA = qb * 128 + w * 16 + (lane >> 2);
    const int colb = (lane & 3) << 1;
#pragma unroll
    for (int nt = 0; nt < 8; nt++) {
        const int col = h * HD + nt * 8 + colb;
        uint32_t h2, l2;
        split2(o[nt][0] * iA, o[nt][1] * iA, h2, l2);
        size_t off = ((size_t)b * SEQ + rA) * EMB + col;
        *(uint32_t*)(g_xh + off) = h2;
        *(uint32_t*)(g_xl + off) = l2;
        split2(o[nt][2] * iB, o[nt][3] * iB, h2, l2);
        off = ((size_t)b * SEQ + rA + 8) * EMB + col;
        *(uint32_t*)(g_xh + off) = h2;
        *(uint32_t*)(g_xl + off) = l2;
    }
}

// ---------------------------------------------------------------------------
extern "C" void kernel_launch(void* const* d_in, const int* in_sizes, int n_in,
                              void* d_out, int out_size) {
    const float* x  = (const float*)d_in[0];
    const int*  mask = (const int*)d_in[1];
    const float* Wq = (const float*)d_in[2];
    const float* bq = (const float*)d_in[3];
    const float* Wk = (const float*)d_in[4];
    const float* bk = (const float*)d_in[5];
    const float* Wv = (const float*)d_in[6];
    const float* bv = (const float*)d_in[7];
    const float* Wo = (const float*)d_in[8];
    const float* bo = (const float*)d_in[9];

    __nv_bfloat16 *xh, *xl, *wh, *wl, *Qh, *Ql, *Kh, *Kl, *Vh, *Vl;
    cudaGetSymbolAddress((void**)&xh, g_xh);
    cudaGetSymbolAddress((void**)&xl, g_xl);
    cudaGetSymbolAddress((void**)&wh, g_wh);
    cudaGetSymbolAddress((void**)&wl, g_wl);
    cudaGetSymbolAddress((void**)&Qh, g_Qh);
    cudaGetSymbolAddress((void**)&Ql, g_Ql);
    cudaGetSymbolAddress((void**)&Kh, g_Kh);
    cudaGetSymbolAddress((void**)&Kl, g_Kl);
    cudaGetSymbolAddress((void**)&Vh, g_Vh);
    cudaGetSymbolAddress((void**)&Vl, g_Vl);
    const size_t WS = (size_t)EMB * EMB;

    const int GEMM_SMEM = 3 * 32768;           // 96KB -> occ 2
    const int ATTN_SMEM = 98304;               // 96KB -> occ 2
    cudaFuncSetAttribute(gemm_mma<1>, cudaFuncAttributeMaxDynamicSharedMemorySize, GEMM_SMEM);
    cudaFuncSetAttribute(gemm_mma<0>, cudaFuncAttributeMaxDynamicSharedMemorySize, GEMM_SMEM);
    cudaFuncSetAttribute(attn_mma,    cudaFuncAttributeMaxDynamicSharedMemorySize, ATTN_SMEM);

    // input split + weight transpose/splits + mask compaction (independent)
    split_kernel<<<(MTOT*EMB)/4/256, 256>>>(x, xh, xl);
    tsplit4_kernel<<<dim3(32,32,4), dim3(32,8)>>>(Wq, Wk, Wv, Wo, wh, wl);
    compact_kernel<<<BSZ, 256>>>(mask);

    // fused QKV projection (z = 0,1,2 -> Q,K,V), bf16 hi/lo out in [B,H,S,D]
    gemm_mma<1><<<dim3(EMB/128, MTOT/128, 3), 256, GEMM_SMEM>>>(
        xh, xl, wh, wl, bq, bk, bv, nullptr, Qh, Ql, Kh, Kl, Vh, Vl);

    // compact K/V by mask (drops ~50% of keys exactly)
    gather_kernel<<<dim3(SEQ/32, NH, BSZ), 256>>>();

    // attention over compacted keys -> bf16 hi/lo activations into xh/xl
    attn_mma<<<dim3(SEQ/128, NH, BSZ), 256, ATTN_SMEM>>>();

    // O projection -> fp32 d_out
    gemm_mma<0><<<dim3(EMB/128, MTOT/128, 1), 256, GEMM_SMEM>>>(
        xh, xl, wh + 3*WS, wl + 3*WS, bo, bo, bo, (float*)d_out,
        nullptr, nullptr, nullptr, nullptr, nullptr, nullptr);
}

// round 11
// speedup vs baseline: 1.5400x; 1.1263x over previous
#include <cuda_runtime.h>
#include <cuda_bf16.h>
#include <math.h>
#include <stdint.h>

#define BSZ 4
#define SEQ 2048
#define EMB 1024
#define NH 16
#define HD 64
#define MTOT (BSZ*SEQ)   // 8192

// ---------------- scratch (__device__ globals; no allocs allowed) ----------
static __device__ __align__(256) __nv_bfloat16 g_xh[(size_t)MTOT*EMB];
static __device__ __align__(256) __nv_bfloat16 g_xl[(size_t)MTOT*EMB];
static __device__ __align__(256) __nv_bfloat16 g_wh[4][(size_t)EMB*EMB];
static __device__ __align__(256) __nv_bfloat16 g_wl[4][(size_t)EMB*EMB];
static __device__ __align__(256) __nv_bfloat16 g_Qh[(size_t)MTOT*EMB];
static __device__ __align__(256) __nv_bfloat16 g_Ql[(size_t)MTOT*EMB];
// compacted x rows (unmasked keys only) — K/V projection input
static __device__ __align__(256) __nv_bfloat16 g_cxh[(size_t)MTOT*EMB];
static __device__ __align__(256) __nv_bfloat16 g_cxl[(size_t)MTOT*EMB];
// mask-compacted K/V (written directly by the K/V projection GEMM)
static __device__ __align__(256) __nv_bfloat16 g_cKh[(size_t)MTOT*EMB];
static __device__ __align__(256) __nv_bfloat16 g_cKl[(size_t)MTOT*EMB];
static __device__ __align__(256) __nv_bfloat16 g_cVh[(size_t)MTOT*EMB];
static __device__ __align__(256) __nv_bfloat16 g_cVl[(size_t)MTOT*EMB];
static __device__ int g_cnt[BSZ];
static __device__ int g_idx[BSZ*SEQ];

// ---------------- helpers --------------------------------------------------
__device__ __forceinline__ uint32_t smem_u32(const void* p) {
    uint32_t a;
    asm("{ .reg .u64 t; cvta.to.shared.u64 t, %1; cvt.u32.u64 %0, t; }"
        : "=r"(a) : "l"(p));
    return a;
}
__device__ __forceinline__ void cp16(uint32_t dst, const void* src) {
    asm volatile("cp.async.cg.shared.global [%0], [%1], 16;" :: "r"(dst), "l"(src));
}
#define CP_COMMIT() asm volatile("cp.async.commit_group;" ::: "memory")
#define CP_WAIT1()  asm volatile("cp.async.wait_group 1;" ::: "memory")
#define CP_WAIT0()  asm volatile("cp.async.wait_group 0;" ::: "memory")

__device__ __forceinline__ void ldsm4(uint32_t r[4], uint32_t a) {
    asm volatile("ldmatrix.sync.aligned.m8n8.x4.shared.b16 {%0,%1,%2,%3}, [%4];"
        : "=r"(r[0]), "=r"(r[1]), "=r"(r[2]), "=r"(r[3]) : "r"(a));
}
__device__ __forceinline__ void ldsm4t(uint32_t r[4], uint32_t a) {
    asm volatile("ldmatrix.sync.aligned.m8n8.x4.trans.shared.b16 {%0,%1,%2,%3}, [%4];"
        : "=r"(r[0]), "=r"(r[1]), "=r"(r[2]), "=r"(r[3]) : "r"(a));
}
__device__ __forceinline__ void mma16816(float c[4], const uint32_t a[4],
                                         uint32_t b0, uint32_t b1) {
    asm volatile("mma.sync.aligned.m16n8k16.row.col.f32.bf16.bf16.f32 "
        "{%0,%1,%2,%3}, {%4,%5,%6,%7}, {%8,%9}, {%0,%1,%2,%3};"
        : "+f"(c[0]), "+f"(c[1]), "+f"(c[2]), "+f"(c[3])
        : "r"(a[0]), "r"(a[1]), "r"(a[2]), "r"(a[3]), "r"(b0), "r"(b1));
}
__device__ __forceinline__ void split2(float v0, float v1, uint32_t& h, uint32_t& l) {
    __nv_bfloat162 hh = __floats2bfloat162_rn(v0, v1);
    float r0 = v0 - __bfloat162float(hh.x);
    float r1 = v1 - __bfloat162float(hh.y);
    __nv_bfloat162 ll = __floats2bfloat162_rn(r0, r1);
    h = *reinterpret_cast<uint32_t*>(&hh);
    l = *reinterpret_cast<uint32_t*>(&ll);
}
// [rows x 64] bf16 tile (128B rows), XOR swizzle: 8 chunks of 16B per row
#define SWZ(r, ch) (((r) << 7) | (((unsigned)((ch) ^ (r)) & 7u) << 4))
// [rows x 32] bf16 tile (64B rows): conflict-free for 8-row ldmatrix groups
#define SWZ32(r, ch) (((r) << 6) | (((unsigned)((ch) ^ (((r) >> 1) & 3)) & 3u) << 4))

// ---------------------------------------------------------------------------
__global__ __launch_bounds__(256)
void split_kernel(const float* __restrict__ src,
                  __nv_bfloat16* __restrict__ hi, __nv_bfloat16* __restrict__ lo) {
    size_t i = (size_t)blockIdx.x * 256 + threadIdx.x;
    float4 v = ((const float4*)src)[i];
    uint32_t h0, l0, h1, l1;
    split2(v.x, v.y, h0, l0);
    split2(v.z, v.w, h1, l1);
    ((uint32_t*)hi)[2*i+0] = h0;  ((uint32_t*)hi)[2*i+1] = h1;
    ((uint32_t*)lo)[2*i+0] = l0;  ((uint32_t*)lo)[2*i+1] = l1;
}

__global__ __launch_bounds__(256)
void tsplit4_kernel(const float* __restrict__ W0, const float* __restrict__ W1,
                    const float* __restrict__ W2, const float* __restrict__ W3,
                    __nv_bfloat16* __restrict__ ThB, __nv_bfloat16* __restrict__ TlB) {
    __shared__ float sm[32][33];
    const int tx = threadIdx.x, ty = threadIdx.y;
    const int n0 = blockIdx.x * 32, k0 = blockIdx.y * 32;
    const int z = blockIdx.z;
    const float* W = (z == 0) ? W0 : (z == 1 ? W1 : (z == 2 ? W2 : W3));
    __nv_bfloat16* Th = ThB + (size_t)z * EMB * EMB;
    __nv_bfloat16* Tl = TlB + (size_t)z * EMB * EMB;
#pragma unroll
    for (int r = ty; r < 32; r += 8)
        sm[r][tx] = W[(size_t)(k0 + r) * EMB + n0 + tx];
    __syncthreads();
#pragma unroll
    for (int r = ty; r < 32; r += 8) {
        float v = sm[tx][r];
        __nv_bfloat16 h = __float2bfloat16_rn(v);
        __nv_bfloat16 l = __float2bfloat16_rn(v - __bfloat162float(h));
        Th[(size_t)(n0 + r) * EMB + k0 + tx] = h;
        Tl[(size_t)(n0 + r) * EMB + k0 + tx] = l;
    }
}

// ---------------------------------------------------------------------------
// per-batch compaction: indices of unmasked keys (order-preserving) + count
// ---------------------------------------------------------------------------
__global__ __launch_bounds__(256)
void compact_kernel(const int* __restrict__ mask) {
    __shared__ int woff[8];
    const int b = blockIdx.x, t = threadIdx.x, lane = t & 31, w = t >> 5;
    const int* m = mask + b * SEQ;
    int v[8], cnt = 0;
#pragma unroll
    for (int i = 0; i < 8; i++) { v[i] = m[t * 8 + i]; cnt += (v[i] != 0); }
    int inc = cnt;
#pragma unroll
    for (int off = 1; off < 32; off <<= 1) {
        int nv = __shfl_up_sync(0xffffffffu, inc, off);
        if (lane >= off) inc += nv;
    }
    if (lane == 31) woff[w] = inc;
    __syncthreads();
    if (t == 0) {
        int run = 0;
#pragma unroll
        for (int j = 0; j < 8; j++) { int tmp = woff[j]; woff[j] = run; run += tmp; }
        g_cnt[b] = run;
    }
    __syncthreads();
    int off = woff[w] + inc - cnt;   // exclusive prefix for this thread
#pragma unroll
    for (int i = 0; i < 8; i++)
        if (v[i]) g_idx[b * SEQ + off++] = t * 8 + i;
}

// gather unmasked x rows (hi/lo) into compacted buffers for K/V projection
__global__ __launch_bounds__(256)
void gatherx_kernel() {
    const int b = blockIdx.y;
    const int j = blockIdx.x * 2 + (threadIdx.x >> 7);
    if (j >= g_cnt[b]) return;
    const int c = (threadIdx.x & 127) << 3;   // 8 bf16 = 16B chunks
    const int src = g_idx[b * SEQ + j];
    const size_t so = ((size_t)(b * SEQ) + src) * EMB + c;
    const size_t dof = ((size_t)(b * SEQ) + j) * EMB + c;
    *(uint4*)(g_cxh + dof) = *(const uint4*)(g_xh + so);
    *(uint4*)(g_cxl + dof) = *(const uint4*)(g_xl + so);
}

// ---------------------------------------------------------------------------
// bf16x3 warp-MMA GEMM. K-chunk 32, 3 stages, occ 2 (R9 machinery).
// HEADOUT=1: z=0 -> Q over all rows; z=1,2 -> K,V over COMPACTED rows only
// (CTAs beyond n_b exit; outputs land directly in compacted [B,H,j,D]).
// HEADOUT=0: plain fp32 row-major GEMM (O projection).
// ---------------------------------------------------------------------------
template<int HEADOUT>
__global__ __launch_bounds__(256, 2)
void gemm_mma(const __nv_bfloat16* __restrict__ Ah, const __nv_bfloat16* __restrict__ Al,
              const __nv_bfloat16* __restrict__ WhBase, const __nv_bfloat16* __restrict__ WlBase,
              const float* __restrict__ b0p, const float* __restrict__ b1p,
              const float* __restrict__ b2p, float* __restrict__ Co,
              __nv_bfloat16* __restrict__ C0h, __nv_bfloat16* __restrict__ C0l,
              __nv_bfloat16* __restrict__ C1h, __nv_bfloat16* __restrict__ C1l,
              __nv_bfloat16* __restrict__ C2h, __nv_bfloat16* __restrict__ C2l) {
    extern __shared__ __align__(128) char smem[];
    const uint32_t sb = smem_u32(smem);
    const int t = threadIdx.x, lane = t & 31, w = t >> 5;
    const int wm = (w & 3) * 32, wn = (w >> 2) * 64;
    const int my = blockIdx.y, n0 = blockIdx.x << 7;
    const int z = HEADOUT ? blockIdx.z : 0;

    // A operand & output routing
    const __nv_bfloat16 *Aph, *Apl;
    int bsel = 0, tile = 0;
    if (HEADOUT && z > 0) {
        bsel = my >> 4; tile = my & 15;
        if ((tile << 7) >= g_cnt[bsel]) return;   // uniform early exit
        const size_t ao = ((size_t)(bsel * SEQ) + ((size_t)tile << 7)) * EMB;
        Aph = g_cxh + ao;  Apl = g_cxl + ao;
    } else {
        const size_t ao = ((size_t)my << 7) * EMB;
        Aph = Ah + ao;  Apl = Al + ao;
    }

    const __nv_bfloat16* Bh = WhBase + (size_t)z * EMB * EMB;
    const __nv_bfloat16* Bl = WlBase + (size_t)z * EMB * EMB;
    const float* bias = (z == 0) ? b0p : (z == 1 ? b1p : b2p);
    __nv_bfloat16* Ch = (z == 0) ? C0h : (z == 1 ? C1h : C2h);
    __nv_bfloat16* Cl = (z == 0) ? C0l : (z == 1 ? C1l : C2l);

    auto issue = [&](int kb, int st) {
        const uint32_t s0 = sb + st * 32768;
        const int kc = kb << 5;
#pragma unroll
        for (int i = 0; i < 2; i++) {
            int idx = t + (i << 8);
            int row = idx >> 2, ch = idx & 3;
            int so = SWZ32(row, ch);
            size_t ga = (size_t)row * EMB + kc + (ch << 3);
            size_t gb = (size_t)(n0 + row) * EMB + kc + (ch << 3);
            cp16(s0 +         so, Aph + ga);
            cp16(s0 +  8192 + so, Apl + ga);
            cp16(s0 + 16384 + so, Bh + gb);
            cp16(s0 + 24576 + so, Bl + gb);
        }
    };

    float c[2][8][4];
#pragma unroll
    for (int i = 0; i < 2; i++)
#pragma unroll
        for (int j = 0; j < 8; j++)
#pragma unroll
            for (int k = 0; k < 4; k++) c[i][j][k] = 0.f;

    issue(0, 0); CP_COMMIT();
    issue(1, 1); CP_COMMIT();

    for (int kb = 0; kb < 32; kb++) {
        CP_WAIT1();
        __syncthreads();
        if (kb + 2 < 32) issue(kb + 2, (kb + 2) % 3);
        CP_COMMIT();

        const uint32_t s0 = sb + (kb % 3) * 32768;
        const uint32_t sAh = s0, sAl = s0 + 8192, sBh = s0 + 16384, sBl = s0 + 24576;
#pragma unroll
        for (int s = 0; s < 2; s++) {
            const int ch = 2 * s + (lane >> 4);
            uint32_t ah[2][4], al[2][4];
#pragma unroll
            for (int mt = 0; mt < 2; mt++) {
                int r = wm + mt * 16 + (lane & 15);
                ldsm4(ah[mt], sAh + SWZ32(r, ch));
                ldsm4(al[mt], sAl + SWZ32(r, ch));
            }
#pragma unroll
            for (int g = 0; g < 4; g++) {
                int r = wn + g * 16 + (lane & 15);
                uint32_t bh[4], bl[4];
                ldsm4(bh, sBh + SWZ32(r, ch));
                ldsm4(bl, sBl + SWZ32(r, ch));
#pragma unroll
                for (int mt = 0; mt < 2; mt++) {
                    mma16816(c[mt][2*g],   ah[mt], bh[0], bh[2]);
                    mma16816(c[mt][2*g+1], ah[mt], bh[1], bh[3]);
                    mma16816(c[mt][2*g],   ah[mt], bl[0], bl[2]);
                    mma16816(c[mt][2*g+1], ah[mt], bl[1], bl[3]);
                    mma16816(c[mt][2*g],   al[mt], bh[0], bh[2]);
                    mma16816(c[mt][2*g+1], al[mt], bh[1], bh[3]);
                }
            }
        }
    }

#pragma unroll
    for (int mt = 0; mt < 2; mt++) {
#pragma unroll
        for (int nt = 0; nt < 8; nt++) {
            const int col = n0 + wn + nt * 8 + ((lane & 3) << 1);
            const float b0 = bias[col], b1 = bias[col + 1];
            const int r0 = wm + mt * 16 + (lane >> 2);   // local row in tile
#pragma unroll
            for (int half = 0; half < 2; half++) {
                const int r = r0 + half * 8;
                const float v0 = c[mt][nt][half*2+0] + b0;
                const float v1 = c[mt][nt][half*2+1] + b1;
                if (HEADOUT) {
                    uint32_t h2, l2;
                    split2(v0, v1, h2, l2);
                    const int hd = col >> 6, d0 = col & 63;
                    size_t off;
                    if (z == 0) {
                        const int m = (my << 7) + r;
                        const int bb = m >> 11, srow = m & 2047;
                        off = (((size_t)(bb * NH + hd)) * SEQ + srow) * HD + d0;
                    } else {
                        const int j = (tile << 7) + r;
                        off = (((size_t)(bsel * NH + hd)) * SEQ + j) * HD + d0;
                    }
                    *(uint32_t*)(Ch + off) = h2;
                    *(uint32_t*)(Cl + off) = l2;
                } else {
                    const int m = (my << 7) + r;
                    *(float2*)(Co + (size_t)m * EMB + col) = make_float2(v0, v1);
                }
            }
        }
    }
}

// ---------------------------------------------------------------------------
// Flash attention over COMPACTED K/V (R10 WIN, unchanged).
// smem: Q 32KB | KV stage0 32KB | KV stage1 32KB = 96KB, occ 2.
// ---------------------------------------------------------------------------
__global__ __launch_bounds__(256, 2)
void attn_mma() {
    extern __shared__ __align__(128) char smem[];
    char* pQh = smem;
    char* pQl = smem + 16384;
    const uint32_t sQh = smem_u32(pQh), sQl = smem_u32(pQl);
    const uint32_t sKV = smem_u32(smem + 32768);

    const int t = threadIdx.x, lane = t & 31, w = t >> 5;
    const int qb = blockIdx.x, h = blockIdx.y, b = blockIdx.z;
    const size_t base = ((size_t)(b * NH + h)) * SEQ * HD;
    const int n = g_cnt[b];
    const int ntiles = (n + 63) >> 6;

    auto issue_kv = [&](int kb, int st) {
        const uint32_t s0 = sKV + st * 32768;
#pragma unroll
        for (int i = 0; i < 2; i++) {
            int idx = t + (i << 8);
            int row = idx >> 3, ch = idx & 7;
            int so = SWZ(row, ch);
            size_t ga = base + (size_t)(kb * 64 + row) * HD + (ch << 3);
            cp16(s0 +         so, g_cKh + ga);
            cp16(s0 +  8192 + so, g_cKl + ga);
            cp16(s0 + 16384 + so, g_cVh + ga);
            cp16(s0 + 24576 + so, g_cVl + ga);
        }
    };

#pragma unroll
    for (int i = 0; i < 4; i++) {
        int idx = t + (i << 8);
        int row = idx >> 3, ch = idx & 7;
        int so = SWZ(row, ch);
        size_t ga = base + (size_t)(qb * 128 + row) * HD + (ch << 3);
        cp16(sQh + so, g_Qh + ga);
        cp16(sQl + so, g_Ql + ga);
    }
    issue_kv(0, 0); CP_COMMIT();

    float o[8][4];
#pragma unroll
    for (int i = 0; i < 8; i++)
#pragma unroll
        for (int j = 0; j < 4; j++) o[i][j] = 0.f;
    float mrow[2] = {-INFINITY, -INFINITY};
    float lsum[2] = {0.f, 0.f};

    for (int kb = 0; kb < ntiles; kb++) {
        CP_WAIT0();
        __syncthreads();
        if (kb + 1 < ntiles) issue_kv(kb + 1, (kb + 1) & 1);
        CP_COMMIT();

        const uint32_t s0 = sKV + (kb & 1) * 32768;
        const uint32_t sKh = s0, sKl = s0 + 8192, sVh = s0 + 16384, sVl = s0 + 24576;

        float c[8][4];
#pragma unroll
        for (int i = 0; i < 8; i++)
#pragma unroll
            for (int j = 0; j < 4; j++) c[i][j] = 0.f;
#pragma unroll
        for (int s = 0; s < 4; s++) {
            const int ch = 2 * s + (lane >> 4);
            uint32_t ah[4], al[4];
            const int rq = w * 16 + (lane & 15);
            ldsm4(ah, sQh + SWZ(rq, ch));
            ldsm4(al, sQl + SWZ(rq, ch));
#pragma unroll
            for (int g = 0; g < 4; g++) {
                const int rk = g * 16 + (lane & 15);
                uint32_t bh[4], bl[4];
                ldsm4(bh, sKh + SWZ(rk, ch));
                ldsm4(bl, sKl + SWZ(rk, ch));
                mma16816(c[2*g],   ah, bh[0], bh[2]);
                mma16816(c[2*g+1], ah, bh[1], bh[3]);
                mma16816(c[2*g],   ah, bl[0], bl[2]);
                mma16816(c[2*g+1], ah, bl[1], bl[3]);
                mma16816(c[2*g],   al, bh[0], bh[2]);
                mma16816(c[2*g+1], al, bh[1], bh[3]);
            }
        }

        // scale + validity select (pad cols -> exactly -1e9 -> weight 0)
        const int cb = (lane & 3) << 1;
#pragma unroll
        for (int nt = 0; nt < 8; nt++) {
            const int col = kb * 64 + nt * 8 + cb;
            const bool v0 = col < n, v1 = col + 1 < n;
            c[nt][0] = v0 ? c[nt][0] * 0.125f : -1.0e9f;
            c[nt][1] = v1 ? c[nt][1] * 0.125f : -1.0e9f;
            c[nt][2] = v0 ? c[nt][2] * 0.125f : -1.0e9f;
            c[nt][3] = v1 ? c[nt][3] * 0.125f : -1.0e9f;
        }

        float mxA = -INFINITY, mxB = -INFINITY;
#pragma unroll
        for (int nt = 0; nt < 8; nt++) {
            mxA = fmaxf(mxA, fmaxf(c[nt][0], c[nt][1]));
            mxB = fmaxf(mxB, fmaxf(c[nt][2], c[nt][3]));
        }
#pragma unroll
        for (int off = 1; off < 4; off <<= 1) {
            mxA = fmaxf(mxA, __shfl_xor_sync(0xffffffffu, mxA, off));
            mxB = fmaxf(mxB, __shfl_xor_sync(0xffffffffu, mxB, off));
        }
        const float nmA = fmaxf(mrow[0], mxA), nmB = fmaxf(mrow[1], mxB);
        const float scA = __expf(mrow[0] - nmA), scB = __expf(mrow[1] - nmB);
        mrow[0] = nmA; mrow[1] = nmB;
        float sA = 0.f, sB = 0.f;
#pragma unroll
        for (int nt = 0; nt < 8; nt++) {
            c[nt][0] = __expf(c[nt][0] - nmA);
            c[nt][1] = __expf(c[nt][1] - nmA);
            c[nt][2] = __expf(c[nt][2] - nmB);
            c[nt][3] = __expf(c[nt][3] - nmB);
            sA += c[nt][0] + c[nt][1];
            sB += c[nt][2] + c[nt][3];
        }
#pragma unroll
        for (int off = 1; off < 4; off <<= 1) {
            sA += __shfl_xor_sync(0xffffffffu, sA, off);
            sB += __shfl_xor_sync(0xffffffffu, sB, off);
        }
        lsum[0] = lsum[0] * scA + sA;
        lsum[1] = lsum[1] * scB + sB;
#pragma unroll
        for (int nt = 0; nt < 8; nt++) {
            o[nt][0] *= scA; o[nt][1] *= scA;
            o[nt][2] *= scB; o[nt][3] *= scB;
        }

#pragma unroll
        for (int kt = 0; kt < 4; kt++) {
            uint32_t ph[4], pl[4];
            split2(c[2*kt][0],   c[2*kt][1],   ph[0], pl[0]);
            split2(c[2*kt][2],   c[2*kt][3],   ph[1], pl[1]);
            split2(c[2*kt+1][0], c[2*kt+1][1], ph[2], pl[2]);
            split2(c[2*kt+1][2], c[2*kt+1][3], ph[3], pl[3]);
            const int rv = kt * 16 + (lane & 15);
#pragma unroll
            for (int g = 0; g < 4; g++) {
                const int chv = 2 * g + (lane >> 4);
                uint32_t vh[4], vl[4];
                ldsm4t(vh, sVh + SWZ(rv, chv));
                ldsm4t(vl, sVl + SWZ(rv, chv));
                mma16816(o[2*g],   ph, vh[0], vh[1]);
                mma16816(o[2*g+1], ph, vh[2], vh[3]);
                mma16816(o[2*g],   ph, vl[0], vl[1]);
                mma16816(o[2*g+1], ph, vl[2], vl[3]);
                mma16816(o[2*g],   pl, vh[0], vh[1]);
                mma16816(o[2*g+1], pl, vh[2], vh[3]);
            }
        }
    }

    const float iA = 1.f / lsum[0], iB = 1.f / lsum[1];
    const int rA = qb * 128 + w * 16 + (lane >> 2);
    const int colb = (lane & 3) << 1;
#pragma unroll
    for (int nt = 0; nt < 8; nt++) {
        const int col = h * HD + nt * 8 + colb;
        uint32_t h2, l2;
        split2(o[nt][0] * iA, o[nt][1] * iA, h2, l2);
        size_t off = ((size_t)b * SEQ + rA) * EMB + col;
        *(uint32_t*)(g_xh + off) = h2;
        *(uint32_t*)(g_xl + off) = l2;
        split2(o[nt][2] * iB, o[nt][3] * iB, h2, l2);
        off = ((size_t)b * SEQ + rA + 8) * EMB + col;
        *(uint32_t*)(g_xh + off) = h2;
        *(uint32_t*)(g_xl + off) = l2;
    }
}

// ---------------------------------------------------------------------------
extern "C" void kernel_launch(void* const* d_in, const int* in_sizes, int n_in,
                              void* d_out, int out_size) {
    const float* x  = (const float*)d_in[0];
    const int*  mask = (const int*)d_in[1];
    const float* Wq = (const float*)d_in[2];
    const float* bq = (const float*)d_in[3];
    const float* Wk = (const float*)d_in[4];
    const float* bk = (const float*)d_in[5];
    const float* Wv = (const float*)d_in[6];
    const float* bv = (const float*)d_in[7];
    const float* Wo = (const float*)d_in[8];
    const float* bo = (const float*)d_in[9];

    __nv_bfloat16 *xh, *xl, *wh, *wl, *Qh, *Ql, *cKh, *cKl, *cVh, *cVl;
    cudaGetSymbolAddress((void**)&xh, g_xh);
    cudaGetSymbolAddress((void**)&xl, g_xl);
    cudaGetSymbolAddress((void**)&wh, g_wh);
    cudaGetSymbolAddress((void**)&wl, g_wl);
    cudaGetSymbolAddress((void**)&Qh, g_Qh);
    cudaGetSymbolAddress((void**)&Ql, g_Ql);
    cudaGetSymbolAddress((void**)&cKh, g_cKh);
    cudaGetSymbolAddress((void**)&cKl, g_cKl);
    cudaGetSymbolAddress((void**)&cVh, g_cVh);
    cudaGetSymbolAddress((void**)&cVl, g_cVl);
    const size_t WS = (size_t)EMB * EMB;

    const int GEMM_SMEM = 3 * 32768;           // 96KB -> occ 2
    const int ATTN_SMEM = 98304;               // 96KB -> occ 2
    cudaFuncSetAttribute(gemm_mma<1>, cudaFuncAttributeMaxDynamicSharedMemorySize, GEMM_SMEM);
    cudaFuncSetAttribute(gemm_mma<0>, cudaFuncAttributeMaxDynamicSharedMemorySize, GEMM_SMEM);
    cudaFuncSetAttribute(attn_mma,    cudaFuncAttributeMaxDynamicSharedMemorySize, ATTN_SMEM);

    // input split + weight transpose/splits + mask compaction (independent)
    split_kernel<<<(MTOT*EMB)/4/256, 256>>>(x, xh, xl);
    tsplit4_kernel<<<dim3(32,32,4), dim3(32,8)>>>(Wq, Wk, Wv, Wo, wh, wl);
    compact_kernel<<<BSZ, 256>>>(mask);

    // gather compacted x rows (K/V projection input)
    gatherx_kernel<<<dim3(SEQ/2, BSZ), 256>>>();

    // fused QKV projection: z=0 Q (all rows), z=1 K / z=2 V (compacted rows,
    // written directly into compacted [B,H,j,D] buffers)
    gemm_mma<1><<<dim3(EMB/128, MTOT/128, 3), 256, GEMM_SMEM>>>(
        xh, xl, wh, wl, bq, bk, bv, nullptr, Qh, Ql, cKh, cKl, cVh, cVl);

    // attention over compacted keys -> bf16 hi/lo activations into xh/xl
    attn_mma<<<dim3(SEQ/128, NH, BSZ), 256, ATTN_SMEM>>>();

    // O projection -> fp32 d_out
    gemm_mma<0><<<dim3(EMB/128, MTOT/128, 1), 256, GEMM_SMEM>>>(
        xh, xl, wh + 3*WS, wl + 3*WS, bo, bo, bo, (float*)d_out,
        nullptr, nullptr, nullptr, nullptr, nullptr, nullptr);
}